// round 4
// baseline (speedup 1.0000x reference)
#include <cuda_runtime.h>
#include <math.h>

#define DEVI __device__ __forceinline__

constexpr int FFT_N  = 1 << 19;          // 524288 = 512 x 1024
constexpr int N1     = 512;              // column FFT length (passes A, C)
constexpr int N2     = 1024;             // row FFT length (pass B)
constexpr int LX     = 960000;
constexpr int KLEN   = 144000;
constexpr int VALID  = FFT_N - KLEN + 1; // 380289
constexpr int NFRAME = 3;
constexpr int NPAIR  = 8;                // 16 batches packed as 8 complex signals
constexpr int NSIG   = NPAIR * NFRAME;   // 24
constexpr float INV_N = 1.0f / (float)FFT_N;
constexpr float TWO_PI = 6.2831853071795865f;

// Static device scratch (allocation-free, graph-safe).
__device__ float2 g_A[(size_t)NSIG * FFT_N];
__device__ float2 g_B[(size_t)NSIG * FFT_N];
__device__ float2 g_hT[FFT_N];
__device__ float2 g_hS[FFT_N];
__device__ float2 g_W1024[1024];   // e^{-2*pi*i*k/1024}
__device__ float2 g_W512[512];     // e^{-2*pi*i*k/512}

DEVI float2 cadd(float2 a, float2 b) { return make_float2(a.x + b.x, a.y + b.y); }
DEVI float2 csub(float2 a, float2 b) { return make_float2(a.x - b.x, a.y - b.y); }
DEVI float2 cmul(float2 a, float2 b) {
    return make_float2(a.x * b.x - a.y * b.y, a.x * b.y + a.y * b.x);
}

template<int SIGN>
DEVI float2 twl(const float2* T, int k) {
    float2 w = __ldg(T + k);
    if (SIGN > 0) w.y = -w.y;
    return w;
}

// ---------------- 8-point DFT in registers, natural in/out ----------------
template<int SIGN>
DEVI void fft8(float2 v[8]) {
    const float C1 = 0.70710678118654752f;
    const float S = (float)SIGN;
    float2 y0 = cadd(v[0], v[4]), z0 = csub(v[0], v[4]);
    float2 y1 = cadd(v[1], v[5]), z1 = csub(v[1], v[5]);
    float2 y2 = cadd(v[2], v[6]), z2 = csub(v[2], v[6]);
    float2 y3 = cadd(v[3], v[7]), z3 = csub(v[3], v[7]);
    z1 = make_float2(C1 * (z1.x - S * z1.y), C1 * (S * z1.x + z1.y));
    z2 = make_float2(-S * z2.y, S * z2.x);
    z3 = make_float2(-C1 * (z3.x + S * z3.y), C1 * (S * z3.x - z3.y));
    {
        float2 t0 = cadd(y0, y2), t1 = csub(y0, y2);
        float2 t2 = cadd(y1, y3), t3 = csub(y1, y3);
        float2 it3 = make_float2(-S * t3.y, S * t3.x);
        v[0] = cadd(t0, t2); v[2] = cadd(t1, it3);
        v[4] = csub(t0, t2); v[6] = csub(t1, it3);
    }
    {
        float2 t0 = cadd(z0, z2), t1 = csub(z0, z2);
        float2 t2 = cadd(z1, z3), t3 = csub(z1, z3);
        float2 it3 = make_float2(-S * t3.y, S * t3.x);
        v[1] = cadd(t0, t2); v[3] = cadd(t1, it3);
        v[5] = csub(t0, t2); v[7] = csub(t1, it3);
    }
}

__global__ void init_luts() {
    int k = blockIdx.x * 256 + threadIdx.x;
    if (k < 1024) {
        double s, c;
        sincospi(-2.0 * (double)k / 1024.0, &s, &c);
        g_W1024[k] = make_float2((float)c, (float)s);
    }
    if (k < 512) {
        double s, c;
        sincospi(-2.0 * (double)k / 512.0, &s, &c);
        g_W512[k] = make_float2((float)c, (float)s);
    }
}

// ============ column-FFT-512 core (4 columns/block, 256 thr, double-buffer) ============
// smem layout: AIDX(row, c) = 4*row + c + (row>>1); verified conflict-free per half-warp.
#define AIDX(row, c) (4 * (row) + (c) + ((row) >> 1))
constexpr int ABUF = AIDX(511, 3) + 1;   // 2303

// ---------------- Pass A (main): gather + column FFT-512 + cross twiddle ----------------
__global__ void __launch_bounds__(256, 4) passA_main(const float* __restrict__ x) {
    __shared__ __align__(16) float2 sb[2][ABUF];
    int sig = blockIdx.x >> 8;
    int cb  = (blockIdx.x & 255) << 2;
    int pair = sig / NFRAME;
    int f    = sig - pair * NFRAME;
    const float* x0 = x + (size_t)(2 * pair) * LX;
    const float* x1 = x0 + LX;

    int c = threadIdx.x & 3, r = threadIdx.x >> 2;   // r in [0,64)
    int n2 = cb + c;
    int pos0 = f * VALID - (KLEN - 1) + r * N2 + n2; // int math, fits easily
    float2 v[8];
#pragma unroll
    for (int j = 0; j < 8; j++) {
        int pos = pos0 + j * (64 * N2);
        float re = 0.f, im = 0.f;
        if (pos >= 0 && pos < LX) { re = __ldg(x0 + pos); im = __ldg(x1 + pos); }
        v[j] = make_float2(re, im);
    }
    // stage 0: s=1, p = r
    fft8<-1>(v);
#pragma unroll
    for (int j = 1; j < 8; j++) v[j] = cmul(v[j], twl<-1>(g_W512, j * r));
#pragma unroll
    for (int j = 0; j < 8; j++) sb[0][AIDX(8 * r + j, c)] = v[j];
    __syncthreads();
    // stage 1: s=8
#pragma unroll
    for (int j = 0; j < 8; j++) v[j] = sb[0][AIDX(r + 64 * j, c)];
    fft8<-1>(v);
    {
        int q = r & 7, p = r >> 3;
#pragma unroll
        for (int j = 1; j < 8; j++) v[j] = cmul(v[j], twl<-1>(g_W512, 8 * j * p));
#pragma unroll
        for (int j = 0; j < 8; j++) sb[1][AIDX(q + 64 * p + 8 * j, c)] = v[j];
    }
    __syncthreads();
    // stage 2: s=64, p=0 (twiddle-free) -> k1 = r + 64j
#pragma unroll
    for (int j = 0; j < 8; j++) v[j] = sb[1][AIDX(r + 64 * j, c)];
    fft8<-1>(v);

    float2* out = g_A + (size_t)sig * FFT_N;
#pragma unroll
    for (int j = 0; j < 8; j++) {
        int k1 = r + 64 * j;
        float fr = (float)(n2 * k1) * INV_N;   // in [0,1)
        float sn, cs;
        __sincosf(-TWO_PI * fr, &sn, &cs);
        out[k1 * N2 + n2] = cmul(v[j], make_float2(cs, sn));
    }
}

// ---------------- Pass A (H): build h, column FFT-512, cross twiddle ----------------
__global__ void __launch_bounds__(256, 4) passA_H(const float* __restrict__ irp) {
    __shared__ __align__(16) float2 sb[2][ABUF];
    int cb = blockIdx.x << 2;
    int c = threadIdx.x & 3, r = threadIdx.x >> 2;
    int n2 = cb + c;
    float2 v[8];
#pragma unroll
    for (int j = 0; j < 8; j++) {
        int n = (r + 64 * j) * N2 + n2;
        float hv = 0.f;
        if (n == 0)         hv = 1.0f;
        else if (n < KLEN)  hv = tanhf(__ldg(irp + KLEN - 1 - n));
        v[j] = make_float2(hv * INV_N, 0.f);
    }
    fft8<-1>(v);
#pragma unroll
    for (int j = 1; j < 8; j++) v[j] = cmul(v[j], twl<-1>(g_W512, j * r));
#pragma unroll
    for (int j = 0; j < 8; j++) sb[0][AIDX(8 * r + j, c)] = v[j];
    __syncthreads();
#pragma unroll
    for (int j = 0; j < 8; j++) v[j] = sb[0][AIDX(r + 64 * j, c)];
    fft8<-1>(v);
    {
        int q = r & 7, p = r >> 3;
#pragma unroll
        for (int j = 1; j < 8; j++) v[j] = cmul(v[j], twl<-1>(g_W512, 8 * j * p));
#pragma unroll
        for (int j = 0; j < 8; j++) sb[1][AIDX(q + 64 * p + 8 * j, c)] = v[j];
    }
    __syncthreads();
#pragma unroll
    for (int j = 0; j < 8; j++) v[j] = sb[1][AIDX(r + 64 * j, c)];
    fft8<-1>(v);
#pragma unroll
    for (int j = 0; j < 8; j++) {
        int k1 = r + 64 * j;
        float fr = (float)(n2 * k1) * INV_N;
        float sn, cs;
        __sincosf(-TWO_PI * fr, &sn, &cs);
        g_hT[k1 * N2 + n2] = cmul(v[j], make_float2(cs, sn));
    }
}

// padded smem index for pass B: +2 per 16 (float4-aligned, <=2-way banks)
#define PD(i) ((i) + ((((i) >> 4)) << 1))

// ---------------- Pass B (H): forward row FFT-1024 (2.8.8.8) ----------------
__global__ void __launch_bounds__(128) passB_H() {
    __shared__ __align__(16) float2 sb[2][1152];
    int k1 = blockIdx.x;
    const float2* rin = g_hT + (size_t)k1 * N2;
    int t = threadIdx.x;
    float2 v[8];
#pragma unroll
    for (int j = 0; j < 8; j++) v[j] = __ldg(rin + t + 128 * j);
#pragma unroll
    for (int m = 0; m < 4; m++) {
        int p = t + 128 * m;
        float2 e = cadd(v[m], v[m + 4]);
        float2 o = cmul(twl<-1>(g_W1024, p), csub(v[m], v[m + 4]));
        *(float4*)&sb[0][PD(2 * p)] = make_float4(e.x, e.y, o.x, o.y);
    }
    __syncthreads();
#pragma unroll
    for (int j = 0; j < 8; j++) v[j] = sb[0][PD(t + 128 * j)];
    fft8<-1>(v);
    {
        int q = t & 1, p = t >> 1;
#pragma unroll
        for (int j = 1; j < 8; j++) v[j] = cmul(v[j], twl<-1>(g_W1024, 2 * j * p));
#pragma unroll
        for (int j = 0; j < 8; j++) sb[1][PD(q + 16 * p + 2 * j)] = v[j];
    }
    __syncthreads();
#pragma unroll
    for (int j = 0; j < 8; j++) v[j] = sb[1][PD(t + 128 * j)];
    fft8<-1>(v);
    {
        int q = t & 15, p = t >> 4;
#pragma unroll
        for (int j = 1; j < 8; j++) v[j] = cmul(v[j], twl<-1>(g_W1024, 16 * j * p));
#pragma unroll
        for (int j = 0; j < 8; j++) sb[0][PD(q + 128 * p + 16 * j)] = v[j];
    }
    __syncthreads();
#pragma unroll
    for (int j = 0; j < 8; j++) v[j] = sb[0][PD(t + 128 * j)];
    fft8<-1>(v);
#pragma unroll
    for (int j = 0; j < 8; j++) g_hS[(size_t)k1 * N2 + t + 128 * j] = v[j];
}

// ---------------- Pass B (main): row FFT-1024 x H, iFFT-1024, inv cross twiddle ----------
__global__ void __launch_bounds__(128) passB_main() {
    __shared__ __align__(16) float2 sb[2][1152];
    int row = blockIdx.x;
    int sig = row >> 9, k1 = row & 511;
    const float2* rin  = g_A + (size_t)sig * FFT_N + (size_t)k1 * N2;
    const float2* hrow = g_hS + (size_t)k1 * N2;
    float2*       rout = g_B + (size_t)sig * FFT_N + (size_t)k1 * N2;
    int t = threadIdx.x;
    float2 v[8];

    // ---- forward ----
#pragma unroll
    for (int j = 0; j < 8; j++) v[j] = __ldg(rin + t + 128 * j);
#pragma unroll
    for (int m = 0; m < 4; m++) {
        int p = t + 128 * m;
        float2 e = cadd(v[m], v[m + 4]);
        float2 o = cmul(twl<-1>(g_W1024, p), csub(v[m], v[m + 4]));
        *(float4*)&sb[0][PD(2 * p)] = make_float4(e.x, e.y, o.x, o.y);
    }
    __syncthreads();
#pragma unroll
    for (int j = 0; j < 8; j++) v[j] = sb[0][PD(t + 128 * j)];
    fft8<-1>(v);
    {
        int q = t & 1, p = t >> 1;
#pragma unroll
        for (int j = 1; j < 8; j++) v[j] = cmul(v[j], twl<-1>(g_W1024, 2 * j * p));
#pragma unroll
        for (int j = 0; j < 8; j++) sb[1][PD(q + 16 * p + 2 * j)] = v[j];
    }
    __syncthreads();
#pragma unroll
    for (int j = 0; j < 8; j++) v[j] = sb[1][PD(t + 128 * j)];
    fft8<-1>(v);
    {
        int q = t & 15, p = t >> 4;
#pragma unroll
        for (int j = 1; j < 8; j++) v[j] = cmul(v[j], twl<-1>(g_W1024, 16 * j * p));
#pragma unroll
        for (int j = 0; j < 8; j++) sb[0][PD(q + 128 * p + 16 * j)] = v[j];
    }
    __syncthreads();
#pragma unroll
    for (int j = 0; j < 8; j++) v[j] = sb[0][PD(t + 128 * j)];
    fft8<-1>(v);

    // ---- pointwise x H ----
#pragma unroll
    for (int j = 0; j < 8; j++) v[j] = cmul(v[j], __ldg(hrow + t + 128 * j));

    // ---- inverse ----
#pragma unroll
    for (int m = 0; m < 4; m++) {
        int p = t + 128 * m;
        float2 e = cadd(v[m], v[m + 4]);
        float2 o = cmul(twl<1>(g_W1024, p), csub(v[m], v[m + 4]));
        *(float4*)&sb[1][PD(2 * p)] = make_float4(e.x, e.y, o.x, o.y);
    }
    __syncthreads();
#pragma unroll
    for (int j = 0; j < 8; j++) v[j] = sb[1][PD(t + 128 * j)];
    fft8<1>(v);
    {
        int q = t & 1, p = t >> 1;
#pragma unroll
        for (int j = 1; j < 8; j++) v[j] = cmul(v[j], twl<1>(g_W1024, 2 * j * p));
#pragma unroll
        for (int j = 0; j < 8; j++) sb[0][PD(q + 16 * p + 2 * j)] = v[j];
    }
    __syncthreads();
#pragma unroll
    for (int j = 0; j < 8; j++) v[j] = sb[0][PD(t + 128 * j)];
    fft8<1>(v);
    {
        int q = t & 15, p = t >> 4;
#pragma unroll
        for (int j = 1; j < 8; j++) v[j] = cmul(v[j], twl<1>(g_W1024, 16 * j * p));
#pragma unroll
        for (int j = 0; j < 8; j++) sb[1][PD(q + 128 * p + 16 * j)] = v[j];
    }
    __syncthreads();
#pragma unroll
    for (int j = 0; j < 8; j++) v[j] = sb[1][PD(t + 128 * j)];
    fft8<1>(v);

#pragma unroll
    for (int j = 0; j < 8; j++) {
        int n2 = t + 128 * j;
        float fr = (float)(n2 * k1) * INV_N;
        float sn, cs;
        __sincosf(TWO_PI * fr, &sn, &cs);
        rout[n2] = cmul(v[j], make_float2(cs, sn));
    }
}

// ---------------- Pass C: column iFFT-512 + overlap-save scatter ----------------
__global__ void __launch_bounds__(256, 4) passC(float* __restrict__ dout) {
    __shared__ __align__(16) float2 sb[2][ABUF];
    int sig = blockIdx.x >> 8;
    int cb  = (blockIdx.x & 255) << 2;
    int pair = sig / NFRAME;
    int f    = sig - pair * NFRAME;
    const float2* in = g_B + (size_t)sig * FFT_N;

    int c = threadIdx.x & 3, r = threadIdx.x >> 2;
    int n2 = cb + c;
    float2 v[8];
#pragma unroll
    for (int j = 0; j < 8; j++) v[j] = __ldg(in + (r + 64 * j) * N2 + n2);
    fft8<1>(v);
#pragma unroll
    for (int j = 1; j < 8; j++) v[j] = cmul(v[j], twl<1>(g_W512, j * r));
#pragma unroll
    for (int j = 0; j < 8; j++) sb[0][AIDX(8 * r + j, c)] = v[j];
    __syncthreads();
#pragma unroll
    for (int j = 0; j < 8; j++) v[j] = sb[0][AIDX(r + 64 * j, c)];
    fft8<1>(v);
    {
        int q = r & 7, p = r >> 3;
#pragma unroll
        for (int j = 1; j < 8; j++) v[j] = cmul(v[j], twl<1>(g_W512, 8 * j * p));
#pragma unroll
        for (int j = 0; j < 8; j++) sb[1][AIDX(q + 64 * p + 8 * j, c)] = v[j];
    }
    __syncthreads();
#pragma unroll
    for (int j = 0; j < 8; j++) v[j] = sb[1][AIDX(r + 64 * j, c)];
    fft8<1>(v);

    int b0 = 2 * pair;
    float* o0 = dout + (size_t)b0 * LX;
    float* o1 = o0 + LX;
#pragma unroll
    for (int j = 0; j < 8; j++) {
        int n1 = r + 64 * j;
        int tt = n1 * N2 + n2 - (KLEN - 1);   // valid-region offset; < VALID always
        if (tt >= 0) {
            int no = f * VALID + tt;
            if (no < LX) {
                o0[no] = v[j].x;
                o1[no] = v[j].y;
            }
        }
    }
}

extern "C" void kernel_launch(void* const* d_in, const int* in_sizes, int n_in,
                              void* d_out, int out_size) {
    (void)in_sizes; (void)n_in; (void)out_size;
    const float* x   = (const float*)d_in[0];
    const float* irp = (const float*)d_in[1];
    float* out = (float*)d_out;

    init_luts<<<4, 256>>>();
    passA_H<<<N2 / 4, 256>>>(irp);           // 256 blocks
    passB_H<<<N1, 128>>>();                  // 512 blocks
    passA_main<<<NSIG * (N2 / 4), 256>>>(x); // 6144 blocks
    passB_main<<<NSIG * N1, 128>>>();        // 12288 blocks
    passC<<<NSIG * (N2 / 4), 256>>>(out);    // 6144 blocks
}

// round 5
// speedup vs baseline: 1.2144x; 1.2144x over previous
#include <cuda_runtime.h>
#include <math.h>

#define DEVI __device__ __forceinline__

constexpr int FFT_N  = 1 << 19;          // 524288 = 512 x 1024
constexpr int N1     = 512;              // column FFT length (passes A, C)
constexpr int N2     = 1024;             // row FFT length (pass B)
constexpr int LX     = 960000;
constexpr int KLEN   = 144000;
constexpr int VALID  = FFT_N - KLEN + 1; // 380289
constexpr int NFRAME = 3;
constexpr int NPAIR  = 8;                // 16 batches packed as 8 complex signals
constexpr int NSIG   = NPAIR * NFRAME;   // 24
constexpr float INV_N = 1.0f / (float)FFT_N;
constexpr float TWO_PI = 6.2831853071795865f;

// Static device scratch (allocation-free, graph-safe).
__device__ float2 g_A[(size_t)NSIG * FFT_N];
__device__ float2 g_B[(size_t)NSIG * FFT_N];
__device__ float2 g_hT[FFT_N];
__device__ float2 g_hS[FFT_N];
__device__ float2 g_W1024[1024];   // e^{-2*pi*i*k/1024}
__device__ float2 g_W512[512];     // e^{-2*pi*i*k/512}

DEVI float2 cadd(float2 a, float2 b) { return make_float2(a.x + b.x, a.y + b.y); }
DEVI float2 csub(float2 a, float2 b) { return make_float2(a.x - b.x, a.y - b.y); }
DEVI float2 cmul(float2 a, float2 b) {
    return make_float2(a.x * b.x - a.y * b.y, a.x * b.y + a.y * b.x);
}

template<int SIGN>
DEVI float2 twl(const float2* T, int k) {
    float2 w = __ldg(T + k);
    if (SIGN > 0) w.y = -w.y;
    return w;
}

// Apply geometric twiddle chain w^1..w^7 to v[1..7].
DEVI void twchain(float2 v[8], float2 w) {
    float2 t = w;
    v[1] = cmul(v[1], t);
#pragma unroll
    for (int j = 2; j < 8; j++) { t = cmul(t, w); v[j] = cmul(v[j], t); }
}

// ---------------- 8-point DFT in registers, natural in/out ----------------
template<int SIGN>
DEVI void fft8(float2 v[8]) {
    const float C1 = 0.70710678118654752f;
    const float S = (float)SIGN;
    float2 y0 = cadd(v[0], v[4]), z0 = csub(v[0], v[4]);
    float2 y1 = cadd(v[1], v[5]), z1 = csub(v[1], v[5]);
    float2 y2 = cadd(v[2], v[6]), z2 = csub(v[2], v[6]);
    float2 y3 = cadd(v[3], v[7]), z3 = csub(v[3], v[7]);
    z1 = make_float2(C1 * (z1.x - S * z1.y), C1 * (S * z1.x + z1.y));
    z2 = make_float2(-S * z2.y, S * z2.x);
    z3 = make_float2(-C1 * (z3.x + S * z3.y), C1 * (S * z3.x - z3.y));
    {
        float2 t0 = cadd(y0, y2), t1 = csub(y0, y2);
        float2 t2 = cadd(y1, y3), t3 = csub(y1, y3);
        float2 it3 = make_float2(-S * t3.y, S * t3.x);
        v[0] = cadd(t0, t2); v[2] = cadd(t1, it3);
        v[4] = csub(t0, t2); v[6] = csub(t1, it3);
    }
    {
        float2 t0 = cadd(z0, z2), t1 = csub(z0, z2);
        float2 t2 = cadd(z1, z3), t3 = csub(z1, z3);
        float2 it3 = make_float2(-S * t3.y, S * t3.x);
        v[1] = cadd(t0, t2); v[3] = cadd(t1, it3);
        v[5] = csub(t0, t2); v[7] = csub(t1, it3);
    }
}

__global__ void init_luts() {
    int k = blockIdx.x * 256 + threadIdx.x;
    if (k < 1024) {
        double s, c;
        sincospi(-2.0 * (double)k / 1024.0, &s, &c);
        g_W1024[k] = make_float2((float)c, (float)s);
    }
    if (k < 512) {
        double s, c;
        sincospi(-2.0 * (double)k / 512.0, &s, &c);
        g_W512[k] = make_float2((float)c, (float)s);
    }
}

// ================= column FFT-512 passes (8 cols x 512 thr, pitch-9 smem) =================

// ---------------- Pass A (main): gather + column FFT-512 (8.8.8) + cross twiddle ----------------
__global__ void __launch_bounds__(512, 2) passA_main(const float* __restrict__ x) {
    __shared__ __align__(16) float2 sb[512 * 9];
    int sig = blockIdx.x >> 7;
    int cb  = (blockIdx.x & 127) << 3;
    int pair = sig / NFRAME;
    int f    = sig - pair * NFRAME;
    const float* x0 = x + (size_t)(2 * pair) * LX;
    const float* x1 = x0 + LX;

    int c = threadIdx.x & 7, r = threadIdx.x >> 3;   // r in [0,64)
    int n2 = cb + c;
    int pos0 = f * VALID - (KLEN - 1) + r * N2 + n2;
    float2 v[8];
#pragma unroll
    for (int j = 0; j < 8; j++) {
        int pos = pos0 + j * (64 * N2);
        float re = 0.f, im = 0.f;
        if (pos >= 0 && pos < LX) { re = __ldg(x0 + pos); im = __ldg(x1 + pos); }
        v[j] = make_float2(re, im);
    }
    // stage 0: s=1, p=r
    fft8<-1>(v);
    twchain(v, twl<-1>(g_W512, r));
#pragma unroll
    for (int j = 0; j < 8; j++) sb[(8 * r + j) * 9 + c] = v[j];
    __syncthreads();
    // stage 1: s=8
#pragma unroll
    for (int j = 0; j < 8; j++) v[j] = sb[(r + 64 * j) * 9 + c];
    fft8<-1>(v);
    {
        int q = r & 7, p = r >> 3;
        twchain(v, twl<-1>(g_W512, 8 * p));
        __syncthreads();
#pragma unroll
        for (int j = 0; j < 8; j++) sb[(q + 64 * p + 8 * j) * 9 + c] = v[j];
    }
    __syncthreads();
    // stage 2: s=64, p=0 (twiddle-free) -> k1 = r + 64j
#pragma unroll
    for (int j = 0; j < 8; j++) v[j] = sb[(r + 64 * j) * 9 + c];
    fft8<-1>(v);

    // cross twiddle chain: W_N^{n2*(r+64j)} = W_N^{n2*r} * (W_8192^{n2})^j
    float sn, cs;
    __sincosf(-TWO_PI * (float)(n2 * r) * INV_N, &sn, &cs);
    float2 cw = make_float2(cs, sn);
    __sincosf(-TWO_PI * (float)n2 * (1.0f / 8192.0f), &sn, &cs);
    float2 stp = make_float2(cs, sn);

    float2* out = g_A + (size_t)sig * FFT_N;
#pragma unroll
    for (int j = 0; j < 8; j++) {
        out[(r + 64 * j) * N2 + n2] = cmul(v[j], cw);
        cw = cmul(cw, stp);
    }
}

// ---------------- Pass A (H): build h, column FFT-512, cross twiddle ----------------
__global__ void __launch_bounds__(512, 2) passA_H(const float* __restrict__ irp) {
    __shared__ __align__(16) float2 sb[512 * 9];
    int cb = blockIdx.x << 3;
    int c = threadIdx.x & 7, r = threadIdx.x >> 3;
    int n2 = cb + c;
    float2 v[8];
#pragma unroll
    for (int j = 0; j < 8; j++) {
        int n = (r + 64 * j) * N2 + n2;
        float hv = 0.f;
        if (n == 0)         hv = 1.0f;
        else if (n < KLEN)  hv = tanhf(__ldg(irp + KLEN - 1 - n));
        v[j] = make_float2(hv * INV_N, 0.f);
    }
    fft8<-1>(v);
    twchain(v, twl<-1>(g_W512, r));
#pragma unroll
    for (int j = 0; j < 8; j++) sb[(8 * r + j) * 9 + c] = v[j];
    __syncthreads();
#pragma unroll
    for (int j = 0; j < 8; j++) v[j] = sb[(r + 64 * j) * 9 + c];
    fft8<-1>(v);
    {
        int q = r & 7, p = r >> 3;
        twchain(v, twl<-1>(g_W512, 8 * p));
        __syncthreads();
#pragma unroll
        for (int j = 0; j < 8; j++) sb[(q + 64 * p + 8 * j) * 9 + c] = v[j];
    }
    __syncthreads();
#pragma unroll
    for (int j = 0; j < 8; j++) v[j] = sb[(r + 64 * j) * 9 + c];
    fft8<-1>(v);

    float sn, cs;
    __sincosf(-TWO_PI * (float)(n2 * r) * INV_N, &sn, &cs);
    float2 cw = make_float2(cs, sn);
    __sincosf(-TWO_PI * (float)n2 * (1.0f / 8192.0f), &sn, &cs);
    float2 stp = make_float2(cs, sn);
#pragma unroll
    for (int j = 0; j < 8; j++) {
        g_hT[(r + 64 * j) * N2 + n2] = cmul(v[j], cw);
        cw = cmul(cw, stp);
    }
}

// padded smem index for pass B: +2 per 16 (float4-aligned, <=2-way banks)
#define PD(i) ((i) + ((((i) >> 4)) << 1))

// ---------------- Pass B (H): forward row FFT-1024 (2.8.8.8) ----------------
__global__ void __launch_bounds__(128) passB_H() {
    __shared__ __align__(16) float2 sb[2][1152];
    int k1 = blockIdx.x;
    const float2* rin = g_hT + (size_t)k1 * N2;
    int t = threadIdx.x;
    float2 v[8];
#pragma unroll
    for (int j = 0; j < 8; j++) v[j] = __ldg(rin + t + 128 * j);
#pragma unroll
    for (int m = 0; m < 4; m++) {
        int p = t + 128 * m;
        float2 e = cadd(v[m], v[m + 4]);
        float2 o = cmul(twl<-1>(g_W1024, p), csub(v[m], v[m + 4]));
        *(float4*)&sb[0][PD(2 * p)] = make_float4(e.x, e.y, o.x, o.y);
    }
    __syncthreads();
#pragma unroll
    for (int j = 0; j < 8; j++) v[j] = sb[0][PD(t + 128 * j)];
    fft8<-1>(v);
    {
        int q = t & 1, p = t >> 1;
        twchain(v, twl<-1>(g_W1024, 2 * p));
#pragma unroll
        for (int j = 0; j < 8; j++) sb[1][PD(q + 16 * p + 2 * j)] = v[j];
    }
    __syncthreads();
#pragma unroll
    for (int j = 0; j < 8; j++) v[j] = sb[1][PD(t + 128 * j)];
    fft8<-1>(v);
    {
        int q = t & 15, p = t >> 4;
        twchain(v, twl<-1>(g_W1024, 16 * p));
#pragma unroll
        for (int j = 0; j < 8; j++) sb[0][PD(q + 128 * p + 16 * j)] = v[j];
    }
    __syncthreads();
#pragma unroll
    for (int j = 0; j < 8; j++) v[j] = sb[0][PD(t + 128 * j)];
    fft8<-1>(v);
#pragma unroll
    for (int j = 0; j < 8; j++) g_hS[(size_t)k1 * N2 + t + 128 * j] = v[j];
}

// ---------------- Pass B (main): row FFT-1024 x H, iFFT-1024, inv cross twiddle ----------
__global__ void __launch_bounds__(128) passB_main() {
    __shared__ __align__(16) float2 sb[2][1152];
    int row = blockIdx.x;
    int sig = row >> 9, k1 = row & 511;
    const float2* rin  = g_A + (size_t)sig * FFT_N + (size_t)k1 * N2;
    const float2* hrow = g_hS + (size_t)k1 * N2;
    float2*       rout = g_B + (size_t)sig * FFT_N + (size_t)k1 * N2;
    int t = threadIdx.x;
    float2 v[8];

    // ---- forward ----
#pragma unroll
    for (int j = 0; j < 8; j++) v[j] = __ldg(rin + t + 128 * j);
#pragma unroll
    for (int m = 0; m < 4; m++) {
        int p = t + 128 * m;
        float2 e = cadd(v[m], v[m + 4]);
        float2 o = cmul(twl<-1>(g_W1024, p), csub(v[m], v[m + 4]));
        *(float4*)&sb[0][PD(2 * p)] = make_float4(e.x, e.y, o.x, o.y);
    }
    __syncthreads();
#pragma unroll
    for (int j = 0; j < 8; j++) v[j] = sb[0][PD(t + 128 * j)];
    fft8<-1>(v);
    {
        int q = t & 1, p = t >> 1;
        twchain(v, twl<-1>(g_W1024, 2 * p));
#pragma unroll
        for (int j = 0; j < 8; j++) sb[1][PD(q + 16 * p + 2 * j)] = v[j];
    }
    __syncthreads();
#pragma unroll
    for (int j = 0; j < 8; j++) v[j] = sb[1][PD(t + 128 * j)];
    fft8<-1>(v);
    {
        int q = t & 15, p = t >> 4;
        twchain(v, twl<-1>(g_W1024, 16 * p));
#pragma unroll
        for (int j = 0; j < 8; j++) sb[0][PD(q + 128 * p + 16 * j)] = v[j];
    }
    __syncthreads();
#pragma unroll
    for (int j = 0; j < 8; j++) v[j] = sb[0][PD(t + 128 * j)];
    fft8<-1>(v);

    // ---- pointwise x H ----
#pragma unroll
    for (int j = 0; j < 8; j++) v[j] = cmul(v[j], __ldg(hrow + t + 128 * j));

    // ---- inverse ----
#pragma unroll
    for (int m = 0; m < 4; m++) {
        int p = t + 128 * m;
        float2 e = cadd(v[m], v[m + 4]);
        float2 o = cmul(twl<1>(g_W1024, p), csub(v[m], v[m + 4]));
        *(float4*)&sb[1][PD(2 * p)] = make_float4(e.x, e.y, o.x, o.y);
    }
    __syncthreads();
#pragma unroll
    for (int j = 0; j < 8; j++) v[j] = sb[1][PD(t + 128 * j)];
    fft8<1>(v);
    {
        int q = t & 1, p = t >> 1;
        twchain(v, twl<1>(g_W1024, 2 * p));
#pragma unroll
        for (int j = 0; j < 8; j++) sb[0][PD(q + 16 * p + 2 * j)] = v[j];
    }
    __syncthreads();
#pragma unroll
    for (int j = 0; j < 8; j++) v[j] = sb[0][PD(t + 128 * j)];
    fft8<1>(v);
    {
        int q = t & 15, p = t >> 4;
        twchain(v, twl<1>(g_W1024, 16 * p));
#pragma unroll
        for (int j = 0; j < 8; j++) sb[1][PD(q + 128 * p + 16 * j)] = v[j];
    }
    __syncthreads();
#pragma unroll
    for (int j = 0; j < 8; j++) v[j] = sb[1][PD(t + 128 * j)];
    fft8<1>(v);

    // inverse cross twiddle chain: W_N^{-(t+128j)*k1 * (-1)} = base * step^j
    float sn, cs;
    __sincosf(TWO_PI * (float)(k1 * t) * INV_N, &sn, &cs);
    float2 cw = make_float2(cs, sn);
    __sincosf(TWO_PI * (float)k1 * (1.0f / 4096.0f), &sn, &cs);
    float2 stp = make_float2(cs, sn);
#pragma unroll
    for (int j = 0; j < 8; j++) {
        rout[t + 128 * j] = cmul(v[j], cw);
        cw = cmul(cw, stp);
    }
}

// ---------------- Pass C: column iFFT-512 + overlap-save scatter ----------------
__global__ void __launch_bounds__(512, 2) passC(float* __restrict__ dout) {
    __shared__ __align__(16) float2 sb[512 * 9];
    int sig = blockIdx.x >> 7;
    int cb  = (blockIdx.x & 127) << 3;
    int pair = sig / NFRAME;
    int f    = sig - pair * NFRAME;
    const float2* in = g_B + (size_t)sig * FFT_N;

    int c = threadIdx.x & 7, r = threadIdx.x >> 3;
    int n2 = cb + c;
    float2 v[8];
#pragma unroll
    for (int j = 0; j < 8; j++) v[j] = __ldg(in + (r + 64 * j) * N2 + n2);
    fft8<1>(v);
    twchain(v, twl<1>(g_W512, r));
#pragma unroll
    for (int j = 0; j < 8; j++) sb[(8 * r + j) * 9 + c] = v[j];
    __syncthreads();
#pragma unroll
    for (int j = 0; j < 8; j++) v[j] = sb[(r + 64 * j) * 9 + c];
    fft8<1>(v);
    {
        int q = r & 7, p = r >> 3;
        twchain(v, twl<1>(g_W512, 8 * p));
        __syncthreads();
#pragma unroll
        for (int j = 0; j < 8; j++) sb[(q + 64 * p + 8 * j) * 9 + c] = v[j];
    }
    __syncthreads();
#pragma unroll
    for (int j = 0; j < 8; j++) v[j] = sb[(r + 64 * j) * 9 + c];
    fft8<1>(v);

    int b0 = 2 * pair;
    float* o0 = dout + (size_t)b0 * LX;
    float* o1 = o0 + LX;
#pragma unroll
    for (int j = 0; j < 8; j++) {
        int n1 = r + 64 * j;
        int tt = n1 * N2 + n2 - (KLEN - 1);   // valid-region offset; < VALID always
        if (tt >= 0) {
            int no = f * VALID + tt;
            if (no < LX) {
                o0[no] = v[j].x;
                o1[no] = v[j].y;
            }
        }
    }
}

extern "C" void kernel_launch(void* const* d_in, const int* in_sizes, int n_in,
                              void* d_out, int out_size) {
    (void)in_sizes; (void)n_in; (void)out_size;
    const float* x   = (const float*)d_in[0];
    const float* irp = (const float*)d_in[1];
    float* out = (float*)d_out;

    init_luts<<<4, 256>>>();
    passA_H<<<N2 / 8, 512>>>(irp);           // 128 blocks
    passB_H<<<N1, 128>>>();                  // 512 blocks
    passA_main<<<NSIG * (N2 / 8), 512>>>(x); // 3072 blocks
    passB_main<<<NSIG * N1, 128>>>();        // 12288 blocks
    passC<<<NSIG * (N2 / 8), 512>>>(out);    // 3072 blocks
}

// round 6
// speedup vs baseline: 1.2752x; 1.0501x over previous
#include <cuda_runtime.h>
#include <math.h>

#define DEVI __device__ __forceinline__

constexpr int FFT_N  = 1 << 19;          // 524288 = 512 x 1024
constexpr int N1     = 512;              // column FFT length (passes A, C)
constexpr int N2     = 1024;             // row FFT length (pass B)
constexpr int LX     = 960000;
constexpr int KLEN   = 144000;
constexpr int VALID  = FFT_N - KLEN + 1; // 380289
constexpr int NFRAME = 3;
constexpr int NPAIR  = 8;                // 16 batches packed as 8 complex signals
constexpr int NSIG   = NPAIR * NFRAME;   // 24
constexpr float INV_N = 1.0f / (float)FFT_N;
constexpr float TWO_PI = 6.2831853071795865f;

// Static device scratch (allocation-free, graph-safe).
__device__ float2 g_A[(size_t)NSIG * FFT_N];
__device__ float2 g_B[(size_t)NSIG * FFT_N];
__device__ float2 g_hT[FFT_N];
__device__ float2 g_hS[FFT_N];
__device__ float2 g_W1024[1024];   // e^{-2*pi*i*k/1024}
__device__ float2 g_W512[512];     // e^{-2*pi*i*k/512}

DEVI float2 cadd(float2 a, float2 b) { return make_float2(a.x + b.x, a.y + b.y); }
DEVI float2 csub(float2 a, float2 b) { return make_float2(a.x - b.x, a.y - b.y); }
DEVI float2 cmul(float2 a, float2 b) {
    return make_float2(a.x * b.x - a.y * b.y, a.x * b.y + a.y * b.x);
}

template<int SIGN>
DEVI float2 twl(const float2* T, int k) {
    float2 w = __ldg(T + k);
    if (SIGN > 0) w.y = -w.y;
    return w;
}

// Apply geometric twiddle chain w^1..w^7 to v[1..7].
DEVI void twchain(float2 v[8], float2 w) {
    float2 t = w;
    v[1] = cmul(v[1], t);
#pragma unroll
    for (int j = 2; j < 8; j++) { t = cmul(t, w); v[j] = cmul(v[j], t); }
}

// Apply geometric twiddle chain w^1..w^15 to v[1..15].
DEVI void twchain16(float2 v[16], float2 w) {
    float2 t = w;
    v[1] = cmul(v[1], t);
#pragma unroll
    for (int j = 2; j < 16; j++) { t = cmul(t, w); v[j] = cmul(v[j], t); }
}

// ---------------- 8-point DFT in registers, natural in/out ----------------
template<int SIGN>
DEVI void fft8(float2 v[8]) {
    const float C1 = 0.70710678118654752f;
    const float S = (float)SIGN;
    float2 y0 = cadd(v[0], v[4]), z0 = csub(v[0], v[4]);
    float2 y1 = cadd(v[1], v[5]), z1 = csub(v[1], v[5]);
    float2 y2 = cadd(v[2], v[6]), z2 = csub(v[2], v[6]);
    float2 y3 = cadd(v[3], v[7]), z3 = csub(v[3], v[7]);
    z1 = make_float2(C1 * (z1.x - S * z1.y), C1 * (S * z1.x + z1.y));
    z2 = make_float2(-S * z2.y, S * z2.x);
    z3 = make_float2(-C1 * (z3.x + S * z3.y), C1 * (S * z3.x - z3.y));
    {
        float2 t0 = cadd(y0, y2), t1 = csub(y0, y2);
        float2 t2 = cadd(y1, y3), t3 = csub(y1, y3);
        float2 it3 = make_float2(-S * t3.y, S * t3.x);
        v[0] = cadd(t0, t2); v[2] = cadd(t1, it3);
        v[4] = csub(t0, t2); v[6] = csub(t1, it3);
    }
    {
        float2 t0 = cadd(z0, z2), t1 = csub(z0, z2);
        float2 t2 = cadd(z1, z3), t3 = csub(z1, z3);
        float2 it3 = make_float2(-S * t3.y, S * t3.x);
        v[1] = cadd(t0, t2); v[3] = cadd(t1, it3);
        v[5] = csub(t0, t2); v[7] = csub(t1, it3);
    }
}

// ---------------- 4-point DFT in registers (in-place on 4 refs) ----------------
template<int SIGN>
DEVI void fft4i(float2& a, float2& b, float2& c, float2& d) {
    const float S = (float)SIGN;
    float2 t0 = cadd(a, c), t1 = csub(a, c);
    float2 t2 = cadd(b, d), t3 = csub(b, d);
    float2 it3 = make_float2(-S * t3.y, S * t3.x);
    a = cadd(t0, t2); b = cadd(t1, it3);
    c = csub(t0, t2); d = csub(t1, it3);
}

// multiply by constant twiddle given as forward (SIGN=-1) value (wr, wi)
template<int SIGN>
DEVI float2 cmw(float2 v, float wr, float wi) {
    return cmul(v, make_float2(wr, SIGN < 0 ? wi : -wi));
}

// ---------------- 16-point DFT in registers, natural in/out (4x4 Stockham) ----------------
template<int SIGN>
DEVI void fft16(float2 v[16]) {
    const float C8  = 0.70710678118654752f;
    const float C16 = 0.92387953251128674f;
    const float S16 = 0.38268343236508977f;
    float2 t[16];
    // stage 1: fft4 on x[r+4j], twiddle W16^{r*j}, store t[4r+j]
    {
        float2 a = v[0], b = v[4], c = v[8], d = v[12];
        fft4i<SIGN>(a, b, c, d);
        t[0] = a; t[1] = b; t[2] = c; t[3] = d;
    }
    {
        float2 a = v[1], b = v[5], c = v[9], d = v[13];
        fft4i<SIGN>(a, b, c, d);
        t[4] = a;
        t[5] = cmw<SIGN>(b,  C16, -S16);   // W16^1
        t[6] = cmw<SIGN>(c,  C8,  -C8);    // W16^2
        t[7] = cmw<SIGN>(d,  S16, -C16);   // W16^3
    }
    {
        float2 a = v[2], b = v[6], c = v[10], d = v[14];
        fft4i<SIGN>(a, b, c, d);
        t[8]  = a;
        t[9]  = cmw<SIGN>(b,  C8,  -C8);   // W16^2
        t[10] = cmw<SIGN>(c,  0.f, -1.f);  // W16^4
        t[11] = cmw<SIGN>(d, -C8,  -C8);   // W16^6
    }
    {
        float2 a = v[3], b = v[7], c = v[11], d = v[15];
        fft4i<SIGN>(a, b, c, d);
        t[12] = a;
        t[13] = cmw<SIGN>(b,  S16, -C16);  // W16^3
        t[14] = cmw<SIGN>(c, -C8,  -C8);   // W16^6
        t[15] = cmw<SIGN>(d, -C16,  S16);  // W16^9
    }
    // stage 2: fft4 on t[r+4j] -> X[r+4j]
#pragma unroll
    for (int r = 0; r < 4; r++) {
        float2 a = t[r], b = t[r + 4], c = t[r + 8], d = t[r + 12];
        fft4i<SIGN>(a, b, c, d);
        v[r] = a; v[r + 4] = b; v[r + 8] = c; v[r + 12] = d;
    }
}

__global__ void init_luts() {
    int k = blockIdx.x * 256 + threadIdx.x;
    if (k < 1024) {
        double s, c;
        sincospi(-2.0 * (double)k / 1024.0, &s, &c);
        g_W1024[k] = make_float2((float)c, (float)s);
    }
    if (k < 512) {
        double s, c;
        sincospi(-2.0 * (double)k / 512.0, &s, &c);
        g_W512[k] = make_float2((float)c, (float)s);
    }
}

// ================= column FFT-512 passes (8 cols x 512 thr, pitch-9 smem) =================

// ---------------- Pass A (main): gather + column FFT-512 (8.8.8) + cross twiddle ----------------
__global__ void __launch_bounds__(512, 3) passA_main(const float* __restrict__ x) {
    __shared__ __align__(16) float2 sb[512 * 9];
    int sig = blockIdx.x >> 7;
    int cb  = (blockIdx.x & 127) << 3;
    int pair = sig / NFRAME;
    int f    = sig - pair * NFRAME;
    const float* x0 = x + (size_t)(2 * pair) * LX;
    const float* x1 = x0 + LX;

    int c = threadIdx.x & 7, r = threadIdx.x >> 3;   // r in [0,64)
    int n2 = cb + c;
    int pos0 = f * VALID - (KLEN - 1) + r * N2 + n2;
    float2 v[8];
#pragma unroll
    for (int j = 0; j < 8; j++) {
        int pos = pos0 + j * (64 * N2);
        float re = 0.f, im = 0.f;
        if (pos >= 0 && pos < LX) { re = __ldg(x0 + pos); im = __ldg(x1 + pos); }
        v[j] = make_float2(re, im);
    }
    fft8<-1>(v);
    twchain(v, twl<-1>(g_W512, r));
#pragma unroll
    for (int j = 0; j < 8; j++) sb[(8 * r + j) * 9 + c] = v[j];
    __syncthreads();
#pragma unroll
    for (int j = 0; j < 8; j++) v[j] = sb[(r + 64 * j) * 9 + c];
    fft8<-1>(v);
    {
        int q = r & 7, p = r >> 3;
        twchain(v, twl<-1>(g_W512, 8 * p));
        __syncthreads();
#pragma unroll
        for (int j = 0; j < 8; j++) sb[(q + 64 * p + 8 * j) * 9 + c] = v[j];
    }
    __syncthreads();
#pragma unroll
    for (int j = 0; j < 8; j++) v[j] = sb[(r + 64 * j) * 9 + c];
    fft8<-1>(v);

    float sn, cs;
    __sincosf(-TWO_PI * (float)(n2 * r) * INV_N, &sn, &cs);
    float2 cw = make_float2(cs, sn);
    __sincosf(-TWO_PI * (float)n2 * (1.0f / 8192.0f), &sn, &cs);
    float2 stp = make_float2(cs, sn);

    float2* out = g_A + (size_t)sig * FFT_N;
#pragma unroll
    for (int j = 0; j < 8; j++) {
        out[(r + 64 * j) * N2 + n2] = cmul(v[j], cw);
        cw = cmul(cw, stp);
    }
}

// ---------------- Pass A (H): build h, column FFT-512, cross twiddle ----------------
__global__ void __launch_bounds__(512, 2) passA_H(const float* __restrict__ irp) {
    __shared__ __align__(16) float2 sb[512 * 9];
    int cb = blockIdx.x << 3;
    int c = threadIdx.x & 7, r = threadIdx.x >> 3;
    int n2 = cb + c;
    float2 v[8];
#pragma unroll
    for (int j = 0; j < 8; j++) {
        int n = (r + 64 * j) * N2 + n2;
        float hv = 0.f;
        if (n == 0)         hv = 1.0f;
        else if (n < KLEN)  hv = tanhf(__ldg(irp + KLEN - 1 - n));
        v[j] = make_float2(hv * INV_N, 0.f);
    }
    fft8<-1>(v);
    twchain(v, twl<-1>(g_W512, r));
#pragma unroll
    for (int j = 0; j < 8; j++) sb[(8 * r + j) * 9 + c] = v[j];
    __syncthreads();
#pragma unroll
    for (int j = 0; j < 8; j++) v[j] = sb[(r + 64 * j) * 9 + c];
    fft8<-1>(v);
    {
        int q = r & 7, p = r >> 3;
        twchain(v, twl<-1>(g_W512, 8 * p));
        __syncthreads();
#pragma unroll
        for (int j = 0; j < 8; j++) sb[(q + 64 * p + 8 * j) * 9 + c] = v[j];
    }
    __syncthreads();
#pragma unroll
    for (int j = 0; j < 8; j++) v[j] = sb[(r + 64 * j) * 9 + c];
    fft8<-1>(v);

    float sn, cs;
    __sincosf(-TWO_PI * (float)(n2 * r) * INV_N, &sn, &cs);
    float2 cw = make_float2(cs, sn);
    __sincosf(-TWO_PI * (float)n2 * (1.0f / 8192.0f), &sn, &cs);
    float2 stp = make_float2(cs, sn);
#pragma unroll
    for (int j = 0; j < 8; j++) {
        g_hT[(r + 64 * j) * N2 + n2] = cmul(v[j], cw);
        cw = cmul(cw, stp);
    }
}

// padded smem index: +2 per 16 (float4-aligned, <=2-way banks)
#define PD(i) ((i) + ((((i) >> 4)) << 1))

// ---------------- Pass B (H): forward row FFT-1024 (2.8.8.8) ----------------
__global__ void __launch_bounds__(128) passB_H() {
    __shared__ __align__(16) float2 sb[2][1152];
    int k1 = blockIdx.x;
    const float2* rin = g_hT + (size_t)k1 * N2;
    int t = threadIdx.x;
    float2 v[8];
#pragma unroll
    for (int j = 0; j < 8; j++) v[j] = __ldg(rin + t + 128 * j);
#pragma unroll
    for (int m = 0; m < 4; m++) {
        int p = t + 128 * m;
        float2 e = cadd(v[m], v[m + 4]);
        float2 o = cmul(twl<-1>(g_W1024, p), csub(v[m], v[m + 4]));
        *(float4*)&sb[0][PD(2 * p)] = make_float4(e.x, e.y, o.x, o.y);
    }
    __syncthreads();
#pragma unroll
    for (int j = 0; j < 8; j++) v[j] = sb[0][PD(t + 128 * j)];
    fft8<-1>(v);
    {
        int q = t & 1, p = t >> 1;
        twchain(v, twl<-1>(g_W1024, 2 * p));
#pragma unroll
        for (int j = 0; j < 8; j++) sb[1][PD(q + 16 * p + 2 * j)] = v[j];
    }
    __syncthreads();
#pragma unroll
    for (int j = 0; j < 8; j++) v[j] = sb[1][PD(t + 128 * j)];
    fft8<-1>(v);
    {
        int q = t & 15, p = t >> 4;
        twchain(v, twl<-1>(g_W1024, 16 * p));
#pragma unroll
        for (int j = 0; j < 8; j++) sb[0][PD(q + 128 * p + 16 * j)] = v[j];
    }
    __syncthreads();
#pragma unroll
    for (int j = 0; j < 8; j++) v[j] = sb[0][PD(t + 128 * j)];
    fft8<-1>(v);
#pragma unroll
    for (int j = 0; j < 8; j++) g_hS[(size_t)k1 * N2 + t + 128 * j] = v[j];
}

// ---------------- Pass B (main): FFT-1024 = 16*16*4, 16 pts/thread, 2 rows/block ----------
// Per row: 64 threads. Smem round trips: 4 (vs 6 for radix-8 version).
__global__ void __launch_bounds__(128, 8) passB_main() {
    __shared__ __align__(16) float2 sb[2][1152];
    int lr = threadIdx.x >> 6;        // local row 0/1
    int t  = threadIdx.x & 63;        // thread within row
    int row = blockIdx.x * 2 + lr;
    int sig = row >> 9, k1 = row & 511;
    const float2* rin  = g_A + (size_t)sig * FFT_N + (size_t)k1 * N2;
    const float2* hrow = g_hS + (size_t)k1 * N2;
    float2*       rout = g_B + (size_t)sig * FFT_N + (size_t)k1 * N2;
    float2* S = sb[lr];

    float2 v[16];
    // ---- fwd stage 0 (R=16, s=1): load x[t+64m], fft16, twiddle W1024^{t*m}, store 16t+m ----
#pragma unroll
    for (int m = 0; m < 16; m++) v[m] = __ldg(rin + t + 64 * m);
    fft16<-1>(v);
    twchain16(v, twl<-1>(g_W1024, t));
    // PD(16t+m) == 18t+m (consecutive): use float4 stores
#pragma unroll
    for (int m = 0; m < 8; m++)
        *(float4*)&S[18 * t + 2 * m] = make_float4(v[2*m].x, v[2*m].y, v[2*m+1].x, v[2*m+1].y);
    __syncthreads();

    // ---- fwd stage 1 (R=16, s=16): load t+64m, fft16, twiddle W64^{p*m}, store q+256p+16m ----
#pragma unroll
    for (int m = 0; m < 16; m++) v[m] = S[PD(t + 64 * m)];
    fft16<-1>(v);
    {
        int q = t & 15, p = t >> 4;
        twchain16(v, twl<-1>(g_W1024, 16 * p));
        __syncthreads();   // all loads done before in-place overwrite
#pragma unroll
        for (int m = 0; m < 16; m++) S[PD(q + 256 * p + 16 * m)] = v[m];
    }
    __syncthreads();

    // ---- fwd stage 2 (R=4, s=256, p=0) -> spectrum regs s16[m'] = X[t + 64*m'] ----
    float2 s16[16];
#pragma unroll
    for (int i = 0; i < 4; i++) {
        float2 a = S[PD(t + 64 * i)];
        float2 b = S[PD(t + 64 * i + 256)];
        float2 c = S[PD(t + 64 * i + 512)];
        float2 d = S[PD(t + 64 * i + 768)];
        fft4i<-1>(a, b, c, d);
        s16[i] = a; s16[i + 4] = b; s16[i + 8] = c; s16[i + 12] = d;
    }

    // ---- pointwise x H (spectrum index t + 64*m') ----
#pragma unroll
    for (int m = 0; m < 16; m++) s16[m] = cmul(s16[m], __ldg(hrow + t + 64 * m));

    // ---- inverse stage 0: fft16, conj twiddle, store 16t+m ----
    fft16<1>(s16);
    twchain16(s16, twl<1>(g_W1024, t));
    __syncthreads();   // fwd stage-2 loads done before overwrite
#pragma unroll
    for (int m = 0; m < 8; m++)
        *(float4*)&S[18 * t + 2 * m] = make_float4(s16[2*m].x, s16[2*m].y, s16[2*m+1].x, s16[2*m+1].y);
    __syncthreads();

    // ---- inverse stage 1 ----
#pragma unroll
    for (int m = 0; m < 16; m++) v[m] = S[PD(t + 64 * m)];
    fft16<1>(v);
    {
        int q = t & 15, p = t >> 4;
        twchain16(v, twl<1>(g_W1024, 16 * p));
        __syncthreads();
#pragma unroll
        for (int m = 0; m < 16; m++) S[PD(q + 256 * p + 16 * m)] = v[m];
    }
    __syncthreads();

    // ---- inverse stage 2 + inverse cross twiddle W_N^{+k1*n2} + store ----
    float sn, cs;
    __sincosf(TWO_PI * (float)(k1 * t) * INV_N, &sn, &cs);
    float2 base = make_float2(cs, sn);
    __sincosf(TWO_PI * (float)k1 * (1.0f / 8192.0f), &sn, &cs);
    float2 A = make_float2(cs, sn);                   // step per i (64)
    __sincosf(TWO_PI * (float)k1 * (1.0f / 2048.0f), &sn, &cs);
    float2 Bm = make_float2(cs, sn);                  // step per m (256)
#pragma unroll
    for (int i = 0; i < 4; i++) {
        float2 a = S[PD(t + 64 * i)];
        float2 b = S[PD(t + 64 * i + 256)];
        float2 c = S[PD(t + 64 * i + 512)];
        float2 d = S[PD(t + 64 * i + 768)];
        fft4i<1>(a, b, c, d);
        float2 w = base;
        rout[t + 64 * i]       = cmul(a, w); w = cmul(w, Bm);
        rout[t + 64 * i + 256] = cmul(b, w); w = cmul(w, Bm);
        rout[t + 64 * i + 512] = cmul(c, w); w = cmul(w, Bm);
        rout[t + 64 * i + 768] = cmul(d, w);
        base = cmul(base, A);
    }
}

// ---------------- Pass C: column iFFT-512 + overlap-save scatter ----------------
__global__ void __launch_bounds__(512, 3) passC(float* __restrict__ dout) {
    __shared__ __align__(16) float2 sb[512 * 9];
    int sig = blockIdx.x >> 7;
    int cb  = (blockIdx.x & 127) << 3;
    int pair = sig / NFRAME;
    int f    = sig - pair * NFRAME;
    const float2* in = g_B + (size_t)sig * FFT_N;

    int c = threadIdx.x & 7, r = threadIdx.x >> 3;
    int n2 = cb + c;
    float2 v[8];
#pragma unroll
    for (int j = 0; j < 8; j++) v[j] = __ldg(in + (r + 64 * j) * N2 + n2);
    fft8<1>(v);
    twchain(v, twl<1>(g_W512, r));
#pragma unroll
    for (int j = 0; j < 8; j++) sb[(8 * r + j) * 9 + c] = v[j];
    __syncthreads();
#pragma unroll
    for (int j = 0; j < 8; j++) v[j] = sb[(r + 64 * j) * 9 + c];
    fft8<1>(v);
    {
        int q = r & 7, p = r >> 3;
        twchain(v, twl<1>(g_W512, 8 * p));
        __syncthreads();
#pragma unroll
        for (int j = 0; j < 8; j++) sb[(q + 64 * p + 8 * j) * 9 + c] = v[j];
    }
    __syncthreads();
#pragma unroll
    for (int j = 0; j < 8; j++) v[j] = sb[(r + 64 * j) * 9 + c];
    fft8<1>(v);

    int b0 = 2 * pair;
    float* o0 = dout + (size_t)b0 * LX;
    float* o1 = o0 + LX;
#pragma unroll
    for (int j = 0; j < 8; j++) {
        int n1 = r + 64 * j;
        int tt = n1 * N2 + n2 - (KLEN - 1);   // valid-region offset; < VALID always
        if (tt >= 0) {
            int no = f * VALID + tt;
            if (no < LX) {
                o0[no] = v[j].x;
                o1[no] = v[j].y;
            }
        }
    }
}

extern "C" void kernel_launch(void* const* d_in, const int* in_sizes, int n_in,
                              void* d_out, int out_size) {
    (void)in_sizes; (void)n_in; (void)out_size;
    const float* x   = (const float*)d_in[0];
    const float* irp = (const float*)d_in[1];
    float* out = (float*)d_out;

    init_luts<<<4, 256>>>();
    passA_H<<<N2 / 8, 512>>>(irp);             // 128 blocks
    passB_H<<<N1, 128>>>();                    // 512 blocks
    passA_main<<<NSIG * (N2 / 8), 512>>>(x);   // 3072 blocks
    passB_main<<<NSIG * N1 / 2, 128>>>();      // 6144 blocks, 2 rows each
    passC<<<NSIG * (N2 / 8), 512>>>(out);      // 3072 blocks
}

// round 7
// speedup vs baseline: 1.3151x; 1.0312x over previous
#include <cuda_runtime.h>
#include <math.h>

#define DEVI __device__ __forceinline__

constexpr int FFT_N  = 1 << 19;          // 524288 = 512 x 1024
constexpr int N1     = 512;              // column FFT length (passes A, C)
constexpr int N2     = 1024;             // row FFT length (pass B)
constexpr int LX     = 960000;
constexpr int KLEN   = 144000;
constexpr int VALID  = FFT_N - KLEN + 1; // 380289
constexpr int NFRAME = 3;
constexpr int NPAIR  = 8;                // 16 batches packed as 8 complex signals
constexpr int NSIG   = NPAIR * NFRAME;   // 24
constexpr float INV_N = 1.0f / (float)FFT_N;
constexpr float TWO_PI = 6.2831853071795865f;

// Static device scratch (allocation-free, graph-safe).
__device__ float2 g_A[(size_t)NSIG * FFT_N];
__device__ float2 g_B[(size_t)NSIG * FFT_N];
__device__ float2 g_hT[FFT_N];
__device__ float2 g_hS[FFT_N];
__device__ float2 g_W1024[1024];   // e^{-2*pi*i*k/1024}
__device__ float2 g_W512[512];     // e^{-2*pi*i*k/512}

DEVI float2 cadd(float2 a, float2 b) { return make_float2(a.x + b.x, a.y + b.y); }
DEVI float2 csub(float2 a, float2 b) { return make_float2(a.x - b.x, a.y - b.y); }
DEVI float2 cmul(float2 a, float2 b) {
    return make_float2(a.x * b.x - a.y * b.y, a.x * b.y + a.y * b.x);
}

template<int SIGN>
DEVI float2 twl(const float2* T, int k) {
    float2 w = __ldg(T + k);
    if (SIGN > 0) w.y = -w.y;
    return w;
}

// Apply geometric twiddle chain w^1..w^7 to v[1..7].
DEVI void twchain(float2 v[8], float2 w) {
    float2 t = w;
    v[1] = cmul(v[1], t);
#pragma unroll
    for (int j = 2; j < 8; j++) { t = cmul(t, w); v[j] = cmul(v[j], t); }
}

// Apply geometric twiddle chain w^1..w^15 to v[1..15].
DEVI void twchain16(float2 v[16], float2 w) {
    float2 t = w;
    v[1] = cmul(v[1], t);
#pragma unroll
    for (int j = 2; j < 16; j++) { t = cmul(t, w); v[j] = cmul(v[j], t); }
}

// ---------------- 8-point DFT in registers, natural in/out ----------------
template<int SIGN>
DEVI void fft8(float2 v[8]) {
    const float C1 = 0.70710678118654752f;
    const float S = (float)SIGN;
    float2 y0 = cadd(v[0], v[4]), z0 = csub(v[0], v[4]);
    float2 y1 = cadd(v[1], v[5]), z1 = csub(v[1], v[5]);
    float2 y2 = cadd(v[2], v[6]), z2 = csub(v[2], v[6]);
    float2 y3 = cadd(v[3], v[7]), z3 = csub(v[3], v[7]);
    z1 = make_float2(C1 * (z1.x - S * z1.y), C1 * (S * z1.x + z1.y));
    z2 = make_float2(-S * z2.y, S * z2.x);
    z3 = make_float2(-C1 * (z3.x + S * z3.y), C1 * (S * z3.x - z3.y));
    {
        float2 t0 = cadd(y0, y2), t1 = csub(y0, y2);
        float2 t2 = cadd(y1, y3), t3 = csub(y1, y3);
        float2 it3 = make_float2(-S * t3.y, S * t3.x);
        v[0] = cadd(t0, t2); v[2] = cadd(t1, it3);
        v[4] = csub(t0, t2); v[6] = csub(t1, it3);
    }
    {
        float2 t0 = cadd(z0, z2), t1 = csub(z0, z2);
        float2 t2 = cadd(z1, z3), t3 = csub(z1, z3);
        float2 it3 = make_float2(-S * t3.y, S * t3.x);
        v[1] = cadd(t0, t2); v[3] = cadd(t1, it3);
        v[5] = csub(t0, t2); v[7] = csub(t1, it3);
    }
}

// ---------------- 4-point DFT in registers (in-place on 4 refs) ----------------
template<int SIGN>
DEVI void fft4i(float2& a, float2& b, float2& c, float2& d) {
    const float S = (float)SIGN;
    float2 t0 = cadd(a, c), t1 = csub(a, c);
    float2 t2 = cadd(b, d), t3 = csub(b, d);
    float2 it3 = make_float2(-S * t3.y, S * t3.x);
    a = cadd(t0, t2); b = cadd(t1, it3);
    c = csub(t0, t2); d = csub(t1, it3);
}

// multiply by constant twiddle given as forward (SIGN=-1) value (wr, wi)
template<int SIGN>
DEVI float2 cmw(float2 v, float wr, float wi) {
    return cmul(v, make_float2(wr, SIGN < 0 ? wi : -wi));
}

// ---------------- 16-point DFT in registers, natural in/out (4x4 Stockham) ----------------
template<int SIGN>
DEVI void fft16(float2 v[16]) {
    const float C8  = 0.70710678118654752f;
    const float C16 = 0.92387953251128674f;
    const float S16 = 0.38268343236508977f;
    float2 t[16];
    {
        float2 a = v[0], b = v[4], c = v[8], d = v[12];
        fft4i<SIGN>(a, b, c, d);
        t[0] = a; t[1] = b; t[2] = c; t[3] = d;
    }
    {
        float2 a = v[1], b = v[5], c = v[9], d = v[13];
        fft4i<SIGN>(a, b, c, d);
        t[4] = a;
        t[5] = cmw<SIGN>(b,  C16, -S16);
        t[6] = cmw<SIGN>(c,  C8,  -C8);
        t[7] = cmw<SIGN>(d,  S16, -C16);
    }
    {
        float2 a = v[2], b = v[6], c = v[10], d = v[14];
        fft4i<SIGN>(a, b, c, d);
        t[8]  = a;
        t[9]  = cmw<SIGN>(b,  C8,  -C8);
        t[10] = cmw<SIGN>(c,  0.f, -1.f);
        t[11] = cmw<SIGN>(d, -C8,  -C8);
    }
    {
        float2 a = v[3], b = v[7], c = v[11], d = v[15];
        fft4i<SIGN>(a, b, c, d);
        t[12] = a;
        t[13] = cmw<SIGN>(b,  S16, -C16);
        t[14] = cmw<SIGN>(c, -C8,  -C8);
        t[15] = cmw<SIGN>(d, -C16,  S16);
    }
#pragma unroll
    for (int r = 0; r < 4; r++) {
        float2 a = t[r], b = t[r + 4], c = t[r + 8], d = t[r + 12];
        fft4i<SIGN>(a, b, c, d);
        v[r] = a; v[r + 4] = b; v[r + 8] = c; v[r + 12] = d;
    }
}

__global__ void init_luts() {
    int k = blockIdx.x * 256 + threadIdx.x;
    if (k < 1024) {
        double s, c;
        sincospi(-2.0 * (double)k / 1024.0, &s, &c);
        g_W1024[k] = make_float2((float)c, (float)s);
    }
    if (k < 512) {
        double s, c;
        sincospi(-2.0 * (double)k / 512.0, &s, &c);
        g_W512[k] = make_float2((float)c, (float)s);
    }
}

// ============ column FFT-512 passes: 16 cols x 512 rows, 512 thr, 16 pts/thread ============
// FFT-512 = 16(s=1) . 16(s=16) . 2(s=256). Thread (c = tid&15, r = tid>>4 in [0,32)).
// smem layout CIDX(n1,c) = n1*17 + c : <=2-way banked for all phases.
#define CIDX(n1, c) ((n1) * 17 + (c))
constexpr int CSMEM_ELEMS = 511 * 17 + 15 + 1;              // 8703
constexpr int CSMEM_BYTES = CSMEM_ELEMS * (int)sizeof(float2); // 69624

// core: given v[m] = input[r + 32m] (m 0..15), run fwd/inv FFT-512 in smem.
// Output: v[m'] = X[r + 32m'] for m' 0..15.
template<int SIGN>
DEVI void col_fft512(float2 v[16], float2* sb, int c, int r) {
    const float2* W = g_W512;
    // stage 0: R=16, s=1, p=r
    fft16<SIGN>(v);
    twchain16(v, twl<SIGN>(W, r));
#pragma unroll
    for (int j = 0; j < 16; j++) sb[CIDX(16 * r + j, c)] = v[j];
    __syncthreads();
    // stage 1: R=16, s=16; q=r&15, p=r>>4; loads at r+32j
#pragma unroll
    for (int j = 0; j < 16; j++) v[j] = sb[CIDX(r + 32 * j, c)];
    fft16<SIGN>(v);
    {
        int q = r & 15, p = r >> 4;
        twchain16(v, twl<SIGN>(W, 16 * p));
        __syncthreads();
#pragma unroll
        for (int j = 0; j < 16; j++) sb[CIDX(q + 256 * p + 16 * j, c)] = v[j];
    }
    __syncthreads();
    // stage 2: R=2, s=256, twiddle-free: pairs (r+32m, r+32m+256)
#pragma unroll
    for (int m = 0; m < 8; m++) {
        float2 a = sb[CIDX(r + 32 * m, c)];
        float2 b = sb[CIDX(r + 32 * m + 256, c)];
        v[m]     = cadd(a, b);
        v[m + 8] = csub(a, b);
    }
}

// ---------------- Pass A (main): gather + column FFT-512 + cross twiddle ----------------
__global__ void __launch_bounds__(512, 2) passA_main(const float* __restrict__ x) {
    extern __shared__ __align__(16) float2 sb[];
    int sig = blockIdx.x >> 6;
    int cb  = (blockIdx.x & 63) << 4;
    int pair = sig / NFRAME;
    int f    = sig - pair * NFRAME;
    const float* x0 = x + (size_t)(2 * pair) * LX;
    const float* x1 = x0 + LX;

    int c = threadIdx.x & 15, r = threadIdx.x >> 4;   // r in [0,32)
    int n2 = cb + c;
    int pos0 = f * VALID - (KLEN - 1) + r * N2 + n2;
    float2 v[16];
#pragma unroll
    for (int m = 0; m < 16; m++) {
        int pos = pos0 + m * (32 * N2);
        float re = 0.f, im = 0.f;
        if (pos >= 0 && pos < LX) { re = __ldg(x0 + pos); im = __ldg(x1 + pos); }
        v[m] = make_float2(re, im);
    }
    col_fft512<-1>(v, sb, c, r);

    // cross twiddle chain: W_N^{n2*(r+32m)} = W_N^{n2*r} * (W_16384^{n2})^m
    float sn, cs;
    __sincosf(-TWO_PI * (float)(n2 * r) * INV_N, &sn, &cs);
    float2 cw = make_float2(cs, sn);
    __sincosf(-TWO_PI * (float)n2 * (1.0f / 16384.0f), &sn, &cs);
    float2 stp = make_float2(cs, sn);

    float2* out = g_A + (size_t)sig * FFT_N;
#pragma unroll
    for (int m = 0; m < 16; m++) {
        out[(r + 32 * m) * N2 + n2] = cmul(v[m], cw);
        cw = cmul(cw, stp);
    }
}

// ---------------- Pass A (H): build h, column FFT-512, cross twiddle ----------------
__global__ void __launch_bounds__(512, 2) passA_H(const float* __restrict__ irp) {
    extern __shared__ __align__(16) float2 sb[];
    int cb = blockIdx.x << 4;
    int c = threadIdx.x & 15, r = threadIdx.x >> 4;
    int n2 = cb + c;
    float2 v[16];
#pragma unroll
    for (int m = 0; m < 16; m++) {
        int n = (r + 32 * m) * N2 + n2;
        float hv = 0.f;
        if (n == 0)         hv = 1.0f;
        else if (n < KLEN)  hv = tanhf(__ldg(irp + KLEN - 1 - n));
        v[m] = make_float2(hv * INV_N, 0.f);
    }
    col_fft512<-1>(v, sb, c, r);

    float sn, cs;
    __sincosf(-TWO_PI * (float)(n2 * r) * INV_N, &sn, &cs);
    float2 cw = make_float2(cs, sn);
    __sincosf(-TWO_PI * (float)n2 * (1.0f / 16384.0f), &sn, &cs);
    float2 stp = make_float2(cs, sn);
#pragma unroll
    for (int m = 0; m < 16; m++) {
        g_hT[(r + 32 * m) * N2 + n2] = cmul(v[m], cw);
        cw = cmul(cw, stp);
    }
}

// padded smem index: +2 per 16 (float4-aligned, <=2-way banks)
#define PD(i) ((i) + ((((i) >> 4)) << 1))

// ---------------- Pass B (H): forward row FFT-1024 (2.8.8.8) ----------------
__global__ void __launch_bounds__(128) passB_H() {
    __shared__ __align__(16) float2 sb[2][1152];
    int k1 = blockIdx.x;
    const float2* rin = g_hT + (size_t)k1 * N2;
    int t = threadIdx.x;
    float2 v[8];
#pragma unroll
    for (int j = 0; j < 8; j++) v[j] = __ldg(rin + t + 128 * j);
#pragma unroll
    for (int m = 0; m < 4; m++) {
        int p = t + 128 * m;
        float2 e = cadd(v[m], v[m + 4]);
        float2 o = cmul(twl<-1>(g_W1024, p), csub(v[m], v[m + 4]));
        *(float4*)&sb[0][PD(2 * p)] = make_float4(e.x, e.y, o.x, o.y);
    }
    __syncthreads();
#pragma unroll
    for (int j = 0; j < 8; j++) v[j] = sb[0][PD(t + 128 * j)];
    fft8<-1>(v);
    {
        int q = t & 1, p = t >> 1;
        twchain(v, twl<-1>(g_W1024, 2 * p));
#pragma unroll
        for (int j = 0; j < 8; j++) sb[1][PD(q + 16 * p + 2 * j)] = v[j];
    }
    __syncthreads();
#pragma unroll
    for (int j = 0; j < 8; j++) v[j] = sb[1][PD(t + 128 * j)];
    fft8<-1>(v);
    {
        int q = t & 15, p = t >> 4;
        twchain(v, twl<-1>(g_W1024, 16 * p));
#pragma unroll
        for (int j = 0; j < 8; j++) sb[0][PD(q + 128 * p + 16 * j)] = v[j];
    }
    __syncthreads();
#pragma unroll
    for (int j = 0; j < 8; j++) v[j] = sb[0][PD(t + 128 * j)];
    fft8<-1>(v);
#pragma unroll
    for (int j = 0; j < 8; j++) g_hS[(size_t)k1 * N2 + t + 128 * j] = v[j];
}

// ---------------- Pass B (main): FFT-1024 = 16*16*4, 16 pts/thread, 2 rows/block ----------
__global__ void __launch_bounds__(128, 8) passB_main() {
    __shared__ __align__(16) float2 sb[2][1152];
    int lr = threadIdx.x >> 6;        // local row 0/1
    int t  = threadIdx.x & 63;        // thread within row
    int row = blockIdx.x * 2 + lr;
    int sig = row >> 9, k1 = row & 511;
    const float2* rin  = g_A + (size_t)sig * FFT_N + (size_t)k1 * N2;
    const float2* hrow = g_hS + (size_t)k1 * N2;
    float2*       rout = g_B + (size_t)sig * FFT_N + (size_t)k1 * N2;
    float2* S = sb[lr];

    float2 v[16];
#pragma unroll
    for (int m = 0; m < 16; m++) v[m] = __ldg(rin + t + 64 * m);
    fft16<-1>(v);
    twchain16(v, twl<-1>(g_W1024, t));
#pragma unroll
    for (int m = 0; m < 8; m++)
        *(float4*)&S[18 * t + 2 * m] = make_float4(v[2*m].x, v[2*m].y, v[2*m+1].x, v[2*m+1].y);
    __syncthreads();

#pragma unroll
    for (int m = 0; m < 16; m++) v[m] = S[PD(t + 64 * m)];
    fft16<-1>(v);
    {
        int q = t & 15, p = t >> 4;
        twchain16(v, twl<-1>(g_W1024, 16 * p));
        __syncthreads();
#pragma unroll
        for (int m = 0; m < 16; m++) S[PD(q + 256 * p + 16 * m)] = v[m];
    }
    __syncthreads();

    float2 s16[16];
#pragma unroll
    for (int i = 0; i < 4; i++) {
        float2 a = S[PD(t + 64 * i)];
        float2 b = S[PD(t + 64 * i + 256)];
        float2 c = S[PD(t + 64 * i + 512)];
        float2 d = S[PD(t + 64 * i + 768)];
        fft4i<-1>(a, b, c, d);
        s16[i] = a; s16[i + 4] = b; s16[i + 8] = c; s16[i + 12] = d;
    }

#pragma unroll
    for (int m = 0; m < 16; m++) s16[m] = cmul(s16[m], __ldg(hrow + t + 64 * m));

    fft16<1>(s16);
    twchain16(s16, twl<1>(g_W1024, t));
    __syncthreads();
#pragma unroll
    for (int m = 0; m < 8; m++)
        *(float4*)&S[18 * t + 2 * m] = make_float4(s16[2*m].x, s16[2*m].y, s16[2*m+1].x, s16[2*m+1].y);
    __syncthreads();

#pragma unroll
    for (int m = 0; m < 16; m++) v[m] = S[PD(t + 64 * m)];
    fft16<1>(v);
    {
        int q = t & 15, p = t >> 4;
        twchain16(v, twl<1>(g_W1024, 16 * p));
        __syncthreads();
#pragma unroll
        for (int m = 0; m < 16; m++) S[PD(q + 256 * p + 16 * m)] = v[m];
    }
    __syncthreads();

    float sn, cs;
    __sincosf(TWO_PI * (float)(k1 * t) * INV_N, &sn, &cs);
    float2 base = make_float2(cs, sn);
    __sincosf(TWO_PI * (float)k1 * (1.0f / 8192.0f), &sn, &cs);
    float2 A = make_float2(cs, sn);
    __sincosf(TWO_PI * (float)k1 * (1.0f / 2048.0f), &sn, &cs);
    float2 Bm = make_float2(cs, sn);
#pragma unroll
    for (int i = 0; i < 4; i++) {
        float2 a = S[PD(t + 64 * i)];
        float2 b = S[PD(t + 64 * i + 256)];
        float2 c = S[PD(t + 64 * i + 512)];
        float2 d = S[PD(t + 64 * i + 768)];
        fft4i<1>(a, b, c, d);
        float2 w = base;
        rout[t + 64 * i]       = cmul(a, w); w = cmul(w, Bm);
        rout[t + 64 * i + 256] = cmul(b, w); w = cmul(w, Bm);
        rout[t + 64 * i + 512] = cmul(c, w); w = cmul(w, Bm);
        rout[t + 64 * i + 768] = cmul(d, w);
        base = cmul(base, A);
    }
}

// ---------------- Pass C: column iFFT-512 + overlap-save scatter ----------------
__global__ void __launch_bounds__(512, 2) passC(float* __restrict__ dout) {
    extern __shared__ __align__(16) float2 sb[];
    int sig = blockIdx.x >> 6;
    int cb  = (blockIdx.x & 63) << 4;
    int pair = sig / NFRAME;
    int f    = sig - pair * NFRAME;
    const float2* in = g_B + (size_t)sig * FFT_N;

    int c = threadIdx.x & 15, r = threadIdx.x >> 4;
    int n2 = cb + c;
    float2 v[16];
#pragma unroll
    for (int m = 0; m < 16; m++) v[m] = __ldg(in + (r + 32 * m) * N2 + n2);
    col_fft512<1>(v, sb, c, r);

    int b0 = 2 * pair;
    float* o0 = dout + (size_t)b0 * LX;
    float* o1 = o0 + LX;
#pragma unroll
    for (int m = 0; m < 16; m++) {
        int n1 = r + 32 * m;
        int tt = n1 * N2 + n2 - (KLEN - 1);   // valid-region offset; < VALID always
        if (tt >= 0) {
            int no = f * VALID + tt;
            if (no < LX) {
                o0[no] = v[m].x;
                o1[no] = v[m].y;
            }
        }
    }
}

extern "C" void kernel_launch(void* const* d_in, const int* in_sizes, int n_in,
                              void* d_out, int out_size) {
    (void)in_sizes; (void)n_in; (void)out_size;
    const float* x   = (const float*)d_in[0];
    const float* irp = (const float*)d_in[1];
    float* out = (float*)d_out;

    // allow >48KB dynamic smem (idempotent host-side attribute set)
    cudaFuncSetAttribute(passA_main, cudaFuncAttributeMaxDynamicSharedMemorySize, CSMEM_BYTES);
    cudaFuncSetAttribute(passA_H,    cudaFuncAttributeMaxDynamicSharedMemorySize, CSMEM_BYTES);
    cudaFuncSetAttribute(passC,      cudaFuncAttributeMaxDynamicSharedMemorySize, CSMEM_BYTES);

    init_luts<<<4, 256>>>();
    passA_H<<<N2 / 16, 512, CSMEM_BYTES>>>(irp);             // 64 blocks
    passB_H<<<N1, 128>>>();                                  // 512 blocks
    passA_main<<<NSIG * (N2 / 16), 512, CSMEM_BYTES>>>(x);   // 1536 blocks
    passB_main<<<NSIG * N1 / 2, 128>>>();                    // 6144 blocks
    passC<<<NSIG * (N2 / 16), 512, CSMEM_BYTES>>>(out);      // 1536 blocks
}

// round 8
// speedup vs baseline: 1.3494x; 1.0261x over previous
#include <cuda_runtime.h>
#include <math.h>

#define DEVI __device__ __forceinline__

constexpr int FFT_N  = 1 << 19;          // 524288 = 512 x 1024
constexpr int N1     = 512;              // column FFT length (passes A, C)
constexpr int N2     = 1024;             // row FFT length (pass B)
constexpr int LX     = 960000;
constexpr int KLEN   = 144000;
constexpr int VALID  = FFT_N - KLEN + 1; // 380289
constexpr int NFRAME = 3;
constexpr int NPAIR  = 8;                // 16 batches packed as 8 complex signals
constexpr int NSIG   = NPAIR * NFRAME;   // 24
constexpr float INV_N = 1.0f / (float)FFT_N;
constexpr float TWO_PI = 6.2831853071795865f;

// Static device scratch (allocation-free, graph-safe).
__device__ float2 g_A[(size_t)NSIG * FFT_N];
__device__ float2 g_B[(size_t)NSIG * FFT_N];
__device__ float2 g_hT[FFT_N];
__device__ float2 g_hS[FFT_N];
__device__ float2 g_W1024[1024];   // e^{-2*pi*i*k/1024}
__device__ float2 g_W512[512];     // e^{-2*pi*i*k/512}

DEVI float2 cadd(float2 a, float2 b) { return make_float2(a.x + b.x, a.y + b.y); }
DEVI float2 csub(float2 a, float2 b) { return make_float2(a.x - b.x, a.y - b.y); }
DEVI float2 cmul(float2 a, float2 b) {
    return make_float2(a.x * b.x - a.y * b.y, a.x * b.y + a.y * b.x);
}

template<int SIGN>
DEVI float2 twl(const float2* T, int k) {
    float2 w = __ldg(T + k);
    if (SIGN > 0) w.y = -w.y;
    return w;
}

// Apply geometric twiddle chain w^1..w^7 to v[1..7] (H pipeline only).
DEVI void twchain(float2 v[8], float2 w) {
    float2 t = w;
    v[1] = cmul(v[1], t);
#pragma unroll
    for (int j = 2; j < 8; j++) { t = cmul(t, w); v[j] = cmul(v[j], t); }
}

// Grouped twiddle apply: w^1..w^15 with depth ~8 (4 parallel chains off w^4 bases).
DEVI void twapply16g(float2 v[16], float2 w) {
    float2 w2  = cmul(w, w);
    float2 w4  = cmul(w2, w2);
    float2 w8  = cmul(w4, w4);
    float2 w12 = cmul(w8, w4);
    float2 t0 = w;
    v[1] = cmul(v[1], t0); t0 = cmul(t0, w);
    v[2] = cmul(v[2], t0); t0 = cmul(t0, w);
    v[3] = cmul(v[3], t0);
    float2 t1 = w4;
    v[4] = cmul(v[4], t1); t1 = cmul(t1, w);
    v[5] = cmul(v[5], t1); t1 = cmul(t1, w);
    v[6] = cmul(v[6], t1); t1 = cmul(t1, w);
    v[7] = cmul(v[7], t1);
    float2 t2 = w8;
    v[8]  = cmul(v[8],  t2); t2 = cmul(t2, w);
    v[9]  = cmul(v[9],  t2); t2 = cmul(t2, w);
    v[10] = cmul(v[10], t2); t2 = cmul(t2, w);
    v[11] = cmul(v[11], t2);
    float2 t3 = w12;
    v[12] = cmul(v[12], t3); t3 = cmul(t3, w);
    v[13] = cmul(v[13], t3); t3 = cmul(t3, w);
    v[14] = cmul(v[14], t3); t3 = cmul(t3, w);
    v[15] = cmul(v[15], t3);
}

// ---------------- 8-point DFT in registers, natural in/out ----------------
template<int SIGN>
DEVI void fft8(float2 v[8]) {
    const float C1 = 0.70710678118654752f;
    const float S = (float)SIGN;
    float2 y0 = cadd(v[0], v[4]), z0 = csub(v[0], v[4]);
    float2 y1 = cadd(v[1], v[5]), z1 = csub(v[1], v[5]);
    float2 y2 = cadd(v[2], v[6]), z2 = csub(v[2], v[6]);
    float2 y3 = cadd(v[3], v[7]), z3 = csub(v[3], v[7]);
    z1 = make_float2(C1 * (z1.x - S * z1.y), C1 * (S * z1.x + z1.y));
    z2 = make_float2(-S * z2.y, S * z2.x);
    z3 = make_float2(-C1 * (z3.x + S * z3.y), C1 * (S * z3.x - z3.y));
    {
        float2 t0 = cadd(y0, y2), t1 = csub(y0, y2);
        float2 t2 = cadd(y1, y3), t3 = csub(y1, y3);
        float2 it3 = make_float2(-S * t3.y, S * t3.x);
        v[0] = cadd(t0, t2); v[2] = cadd(t1, it3);
        v[4] = csub(t0, t2); v[6] = csub(t1, it3);
    }
    {
        float2 t0 = cadd(z0, z2), t1 = csub(z0, z2);
        float2 t2 = cadd(z1, z3), t3 = csub(z1, z3);
        float2 it3 = make_float2(-S * t3.y, S * t3.x);
        v[1] = cadd(t0, t2); v[3] = cadd(t1, it3);
        v[5] = csub(t0, t2); v[7] = csub(t1, it3);
    }
}

// ---------------- 4-point DFT in registers (in-place on 4 refs) ----------------
template<int SIGN>
DEVI void fft4i(float2& a, float2& b, float2& c, float2& d) {
    const float S = (float)SIGN;
    float2 t0 = cadd(a, c), t1 = csub(a, c);
    float2 t2 = cadd(b, d), t3 = csub(b, d);
    float2 it3 = make_float2(-S * t3.y, S * t3.x);
    a = cadd(t0, t2); b = cadd(t1, it3);
    c = csub(t0, t2); d = csub(t1, it3);
}

// multiply by constant twiddle given as forward (SIGN=-1) value (wr, wi)
template<int SIGN>
DEVI float2 cmw(float2 v, float wr, float wi) {
    return cmul(v, make_float2(wr, SIGN < 0 ? wi : -wi));
}

// ---------------- 16-point DFT in registers, natural in/out (4x4 Stockham) ----------------
template<int SIGN>
DEVI void fft16(float2 v[16]) {
    const float C8  = 0.70710678118654752f;
    const float C16 = 0.92387953251128674f;
    const float S16 = 0.38268343236508977f;
    float2 t[16];
    {
        float2 a = v[0], b = v[4], c = v[8], d = v[12];
        fft4i<SIGN>(a, b, c, d);
        t[0] = a; t[1] = b; t[2] = c; t[3] = d;
    }
    {
        float2 a = v[1], b = v[5], c = v[9], d = v[13];
        fft4i<SIGN>(a, b, c, d);
        t[4] = a;
        t[5] = cmw<SIGN>(b,  C16, -S16);
        t[6] = cmw<SIGN>(c,  C8,  -C8);
        t[7] = cmw<SIGN>(d,  S16, -C16);
    }
    {
        float2 a = v[2], b = v[6], c = v[10], d = v[14];
        fft4i<SIGN>(a, b, c, d);
        t[8]  = a;
        t[9]  = cmw<SIGN>(b,  C8,  -C8);
        t[10] = cmw<SIGN>(c,  0.f, -1.f);
        t[11] = cmw<SIGN>(d, -C8,  -C8);
    }
    {
        float2 a = v[3], b = v[7], c = v[11], d = v[15];
        fft4i<SIGN>(a, b, c, d);
        t[12] = a;
        t[13] = cmw<SIGN>(b,  S16, -C16);
        t[14] = cmw<SIGN>(c, -C8,  -C8);
        t[15] = cmw<SIGN>(d, -C16,  S16);
    }
#pragma unroll
    for (int r = 0; r < 4; r++) {
        float2 a = t[r], b = t[r + 4], c = t[r + 8], d = t[r + 12];
        fft4i<SIGN>(a, b, c, d);
        v[r] = a; v[r + 4] = b; v[r + 8] = c; v[r + 12] = d;
    }
}

__global__ void init_luts() {
    int k = blockIdx.x * 256 + threadIdx.x;
    if (k < 1024) {
        double s, c;
        sincospi(-2.0 * (double)k / 1024.0, &s, &c);
        g_W1024[k] = make_float2((float)c, (float)s);
    }
    if (k < 512) {
        double s, c;
        sincospi(-2.0 * (double)k / 512.0, &s, &c);
        g_W512[k] = make_float2((float)c, (float)s);
    }
}

// ============ column FFT-512 passes: 16 cols x 512 rows, 512 thr, 16 pts/thread ============
// FFT-512 = 16(s=1) . 16(s=16) . 2(s=256). Thread (c = tid&15, r = tid>>4 in [0,32)).
// smem layout CIDX(n1,c) = n1*17 + c : <=2-way banked for all phases.
#define CIDX(n1, c) ((n1) * 17 + (c))
constexpr int CSMEM_ELEMS = 511 * 17 + 15 + 1;              // 8703
constexpr int CSMEM_BYTES = CSMEM_ELEMS * (int)sizeof(float2); // 69624

// core: given v[m] = input[r + 32m], run fwd/inv FFT-512 in smem.
// Stage twiddles via per-j LUT: warp spans only 2 r-values -> broadcast LDG, depth 1.
template<int SIGN>
DEVI void col_fft512(float2 v[16], float2* sb, int c, int r) {
    const float2* W = g_W512;
    // stage 0: R=16, s=1, p=r, twiddle W512^{j*r} (j*r <= 465)
    fft16<SIGN>(v);
#pragma unroll
    for (int j = 1; j < 16; j++) v[j] = cmul(v[j], twl<SIGN>(W, j * r));
#pragma unroll
    for (int j = 0; j < 16; j++) sb[CIDX(16 * r + j, c)] = v[j];
    __syncthreads();
    // stage 1: R=16, s=16; q=r&15, p=r>>4 (warp-uniform); twiddle W512^{16*j*p}
#pragma unroll
    for (int j = 0; j < 16; j++) v[j] = sb[CIDX(r + 32 * j, c)];
    fft16<SIGN>(v);
    {
        int q = r & 15, p = r >> 4;
        if (p) {
#pragma unroll
            for (int j = 1; j < 16; j++) v[j] = cmul(v[j], twl<SIGN>(W, 16 * j));
        }
        __syncthreads();
#pragma unroll
        for (int j = 0; j < 16; j++) sb[CIDX(q + 256 * p + 16 * j, c)] = v[j];
    }
    __syncthreads();
    // stage 2: R=2, s=256, twiddle-free: pairs (r+32m, r+32m+256)
#pragma unroll
    for (int m = 0; m < 8; m++) {
        float2 a = sb[CIDX(r + 32 * m, c)];
        float2 b = sb[CIDX(r + 32 * m + 256, c)];
        v[m]     = cadd(a, b);
        v[m + 8] = csub(a, b);
    }
}

// ---------------- Pass A (main): gather + column FFT-512 + cross twiddle ----------------
__global__ void __launch_bounds__(512, 2) passA_main(const float* __restrict__ x) {
    extern __shared__ __align__(16) float2 sb[];
    int sig = blockIdx.x >> 6;
    int cb  = (blockIdx.x & 63) << 4;
    int pair = sig / NFRAME;
    int f    = sig - pair * NFRAME;
    const float* x0 = x + (size_t)(2 * pair) * LX;
    const float* x1 = x0 + LX;

    int c = threadIdx.x & 15, r = threadIdx.x >> 4;   // r in [0,32)
    int n2 = cb + c;
    int pos0 = f * VALID - (KLEN - 1) + r * N2 + n2;
    float2 v[16];
#pragma unroll
    for (int m = 0; m < 16; m++) {
        int pos = pos0 + m * (32 * N2);
        float re = 0.f, im = 0.f;
        if (pos >= 0 && pos < LX) { re = __ldg(x0 + pos); im = __ldg(x1 + pos); }
        v[m] = make_float2(re, im);
    }
    col_fft512<-1>(v, sb, c, r);

    // cross twiddle W_N^{n2*(r+32m)} = base * stp^m ; 4 parallel store streams
    float sn, cs;
    __sincosf(-TWO_PI * (float)(n2 * r) * INV_N, &sn, &cs);
    float2 base = make_float2(cs, sn);
    __sincosf(-TWO_PI * (float)n2 * (1.0f / 16384.0f), &sn, &cs);
    float2 stp = make_float2(cs, sn);
    float2 stp2 = cmul(stp, stp);
    float2 stp4 = cmul(stp2, stp2);
    float2 b0 = base;
    float2 b1 = cmul(b0, stp4);
    float2 b2 = cmul(b1, stp4);
    float2 b3 = cmul(b2, stp4);

    float2* out = g_A + (size_t)sig * FFT_N;
#pragma unroll
    for (int e = 0; e < 4; e++) {
        out[(r + 32 * (e))      * N2 + n2] = cmul(v[e],      b0);
        out[(r + 32 * (e + 4))  * N2 + n2] = cmul(v[e + 4],  b1);
        out[(r + 32 * (e + 8))  * N2 + n2] = cmul(v[e + 8],  b2);
        out[(r + 32 * (e + 12)) * N2 + n2] = cmul(v[e + 12], b3);
        if (e < 3) {
            b0 = cmul(b0, stp); b1 = cmul(b1, stp);
            b2 = cmul(b2, stp); b3 = cmul(b3, stp);
        }
    }
}

// ---------------- Pass A (H): build h, column FFT-512, cross twiddle ----------------
__global__ void __launch_bounds__(512, 2) passA_H(const float* __restrict__ irp) {
    extern __shared__ __align__(16) float2 sb[];
    int cb = blockIdx.x << 4;
    int c = threadIdx.x & 15, r = threadIdx.x >> 4;
    int n2 = cb + c;
    float2 v[16];
#pragma unroll
    for (int m = 0; m < 16; m++) {
        int n = (r + 32 * m) * N2 + n2;
        float hv = 0.f;
        if (n == 0)         hv = 1.0f;
        else if (n < KLEN)  hv = tanhf(__ldg(irp + KLEN - 1 - n));
        v[m] = make_float2(hv * INV_N, 0.f);
    }
    col_fft512<-1>(v, sb, c, r);

    float sn, cs;
    __sincosf(-TWO_PI * (float)(n2 * r) * INV_N, &sn, &cs);
    float2 cw = make_float2(cs, sn);
    __sincosf(-TWO_PI * (float)n2 * (1.0f / 16384.0f), &sn, &cs);
    float2 stp = make_float2(cs, sn);
#pragma unroll
    for (int m = 0; m < 16; m++) {
        g_hT[(r + 32 * m) * N2 + n2] = cmul(v[m], cw);
        cw = cmul(cw, stp);
    }
}

// padded smem index: +2 per 16 (float4-aligned, <=2-way banks)
#define PD(i) ((i) + ((((i) >> 4)) << 1))

// ---------------- Pass B (H): forward row FFT-1024 (2.8.8.8) ----------------
__global__ void __launch_bounds__(128) passB_H() {
    __shared__ __align__(16) float2 sb[2][1152];
    int k1 = blockIdx.x;
    const float2* rin = g_hT + (size_t)k1 * N2;
    int t = threadIdx.x;
    float2 v[8];
#pragma unroll
    for (int j = 0; j < 8; j++) v[j] = __ldg(rin + t + 128 * j);
#pragma unroll
    for (int m = 0; m < 4; m++) {
        int p = t + 128 * m;
        float2 e = cadd(v[m], v[m + 4]);
        float2 o = cmul(twl<-1>(g_W1024, p), csub(v[m], v[m + 4]));
        *(float4*)&sb[0][PD(2 * p)] = make_float4(e.x, e.y, o.x, o.y);
    }
    __syncthreads();
#pragma unroll
    for (int j = 0; j < 8; j++) v[j] = sb[0][PD(t + 128 * j)];
    fft8<-1>(v);
    {
        int q = t & 1, p = t >> 1;
        twchain(v, twl<-1>(g_W1024, 2 * p));
#pragma unroll
        for (int j = 0; j < 8; j++) sb[1][PD(q + 16 * p + 2 * j)] = v[j];
    }
    __syncthreads();
#pragma unroll
    for (int j = 0; j < 8; j++) v[j] = sb[1][PD(t + 128 * j)];
    fft8<-1>(v);
    {
        int q = t & 15, p = t >> 4;
        twchain(v, twl<-1>(g_W1024, 16 * p));
#pragma unroll
        for (int j = 0; j < 8; j++) sb[0][PD(q + 128 * p + 16 * j)] = v[j];
    }
    __syncthreads();
#pragma unroll
    for (int j = 0; j < 8; j++) v[j] = sb[0][PD(t + 128 * j)];
    fft8<-1>(v);
#pragma unroll
    for (int j = 0; j < 8; j++) g_hS[(size_t)k1 * N2 + t + 128 * j] = v[j];
}

// ---------------- Pass B (main): FFT-1024 = 16*16*4, 16 pts/thread, 2 rows/block ----------
__global__ void __launch_bounds__(128, 8) passB_main() {
    __shared__ __align__(16) float2 sb[2][1152];
    int lr = threadIdx.x >> 6;        // local row 0/1
    int t  = threadIdx.x & 63;        // thread within row
    int row = blockIdx.x * 2 + lr;
    int sig = row >> 9, k1 = row & 511;
    const float2* rin  = g_A + (size_t)sig * FFT_N + (size_t)k1 * N2;
    const float2* hrow = g_hS + (size_t)k1 * N2;
    float2*       rout = g_B + (size_t)sig * FFT_N + (size_t)k1 * N2;
    float2* S = sb[lr];

    float2 v[16];
#pragma unroll
    for (int m = 0; m < 16; m++) v[m] = __ldg(rin + t + 64 * m);
    fft16<-1>(v);
    twapply16g(v, twl<-1>(g_W1024, t));
#pragma unroll
    for (int m = 0; m < 8; m++)
        *(float4*)&S[18 * t + 2 * m] = make_float4(v[2*m].x, v[2*m].y, v[2*m+1].x, v[2*m+1].y);
    __syncthreads();

#pragma unroll
    for (int m = 0; m < 16; m++) v[m] = S[PD(t + 64 * m)];
    fft16<-1>(v);
    {
        int q = t & 15, p = t >> 4;
        twapply16g(v, twl<-1>(g_W1024, 16 * p));
        __syncthreads();
#pragma unroll
        for (int m = 0; m < 16; m++) S[PD(q + 256 * p + 16 * m)] = v[m];
    }
    __syncthreads();

    float2 s16[16];
#pragma unroll
    for (int i = 0; i < 4; i++) {
        float2 a = S[PD(t + 64 * i)];
        float2 b = S[PD(t + 64 * i + 256)];
        float2 c = S[PD(t + 64 * i + 512)];
        float2 d = S[PD(t + 64 * i + 768)];
        fft4i<-1>(a, b, c, d);
        s16[i] = a; s16[i + 4] = b; s16[i + 8] = c; s16[i + 12] = d;
    }

#pragma unroll
    for (int m = 0; m < 16; m++) s16[m] = cmul(s16[m], __ldg(hrow + t + 64 * m));

    fft16<1>(s16);
    twapply16g(s16, twl<1>(g_W1024, t));
    __syncthreads();
#pragma unroll
    for (int m = 0; m < 8; m++)
        *(float4*)&S[18 * t + 2 * m] = make_float4(s16[2*m].x, s16[2*m].y, s16[2*m+1].x, s16[2*m+1].y);
    __syncthreads();

#pragma unroll
    for (int m = 0; m < 16; m++) v[m] = S[PD(t + 64 * m)];
    fft16<1>(v);
    {
        int q = t & 15, p = t >> 4;
        twapply16g(v, twl<1>(g_W1024, 16 * p));
        __syncthreads();
#pragma unroll
        for (int m = 0; m < 16; m++) S[PD(q + 256 * p + 16 * m)] = v[m];
    }
    __syncthreads();

    float sn, cs;
    __sincosf(TWO_PI * (float)(k1 * t) * INV_N, &sn, &cs);
    float2 base = make_float2(cs, sn);
    __sincosf(TWO_PI * (float)k1 * (1.0f / 8192.0f), &sn, &cs);
    float2 A = make_float2(cs, sn);
    __sincosf(TWO_PI * (float)k1 * (1.0f / 2048.0f), &sn, &cs);
    float2 Bm = make_float2(cs, sn);
    // precompute outer bases (depth 3) so the 4 outer groups store in parallel
    float2 ob[4];
    ob[0] = base;
    ob[1] = cmul(base, A);
    ob[2] = cmul(ob[1], A);
    ob[3] = cmul(ob[2], A);
#pragma unroll
    for (int i = 0; i < 4; i++) {
        float2 a = S[PD(t + 64 * i)];
        float2 b = S[PD(t + 64 * i + 256)];
        float2 c = S[PD(t + 64 * i + 512)];
        float2 d = S[PD(t + 64 * i + 768)];
        fft4i<1>(a, b, c, d);
        float2 w = ob[i];
        rout[t + 64 * i]       = cmul(a, w); w = cmul(w, Bm);
        rout[t + 64 * i + 256] = cmul(b, w); w = cmul(w, Bm);
        rout[t + 64 * i + 512] = cmul(c, w); w = cmul(w, Bm);
        rout[t + 64 * i + 768] = cmul(d, w);
    }
}

// ---------------- Pass C: column iFFT-512 + overlap-save scatter ----------------
__global__ void __launch_bounds__(512, 2) passC(float* __restrict__ dout) {
    extern __shared__ __align__(16) float2 sb[];
    int sig = blockIdx.x >> 6;
    int cb  = (blockIdx.x & 63) << 4;
    int pair = sig / NFRAME;
    int f    = sig - pair * NFRAME;
    const float2* in = g_B + (size_t)sig * FFT_N;

    int c = threadIdx.x & 15, r = threadIdx.x >> 4;
    int n2 = cb + c;
    float2 v[16];
#pragma unroll
    for (int m = 0; m < 16; m++) v[m] = __ldg(in + (r + 32 * m) * N2 + n2);
    col_fft512<1>(v, sb, c, r);

    int b0 = 2 * pair;
    float* o0 = dout + (size_t)b0 * LX;
    float* o1 = o0 + LX;
#pragma unroll
    for (int m = 0; m < 16; m++) {
        int n1 = r + 32 * m;
        int tt = n1 * N2 + n2 - (KLEN - 1);   // valid-region offset; < VALID always
        if (tt >= 0) {
            int no = f * VALID + tt;
            if (no < LX) {
                o0[no] = v[m].x;
                o1[no] = v[m].y;
            }
        }
    }
}

extern "C" void kernel_launch(void* const* d_in, const int* in_sizes, int n_in,
                              void* d_out, int out_size) {
    (void)in_sizes; (void)n_in; (void)out_size;
    const float* x   = (const float*)d_in[0];
    const float* irp = (const float*)d_in[1];
    float* out = (float*)d_out;

    cudaFuncSetAttribute(passA_main, cudaFuncAttributeMaxDynamicSharedMemorySize, CSMEM_BYTES);
    cudaFuncSetAttribute(passA_H,    cudaFuncAttributeMaxDynamicSharedMemorySize, CSMEM_BYTES);
    cudaFuncSetAttribute(passC,      cudaFuncAttributeMaxDynamicSharedMemorySize, CSMEM_BYTES);

    init_luts<<<4, 256>>>();
    passA_H<<<N2 / 16, 512, CSMEM_BYTES>>>(irp);             // 64 blocks
    passB_H<<<N1, 128>>>();                                  // 512 blocks
    passA_main<<<NSIG * (N2 / 16), 512, CSMEM_BYTES>>>(x);   // 1536 blocks
    passB_main<<<NSIG * N1 / 2, 128>>>();                    // 6144 blocks
    passC<<<NSIG * (N2 / 16), 512, CSMEM_BYTES>>>(out);      // 1536 blocks
}